// round 11
// baseline (speedup 1.0000x reference)
#include <cuda_runtime.h>
#include <cstdint>

// Problem constants
#define B_  8
#define C_  512          // channels == D
#define N_  16384        // H*W
#define K_  150          // num classes
#define KP  160          // K padded (rpart stride)
#define KP2 192          // K padded to BK multiple (h rows, STT cols)
#define NSPLIT 16
#define CHUNK (N_ / NSPLIT)   // 1024

// Tile config
#define BM  128
#define BN  160
#define BK  64
#define BMp 136   // pad: conflict-free [k][m] frag reads
#define BKp 68    // pad: conflict-free [n][k] frag reads

// stage size (words): As(64*BMp = 8704 | 128*BKp = 8704) + Bs(160*BKp = 10880)
#define STG   19584
#define ABOFF 8704            // Bs offset within a stage (same for both shapes)
#define CS_W  (BN * BMp)      // 21760

#define SMEM_GEMM_B  (2 * STG * 4)            // 156672
#define CI_OFF  (2 * STG)
#define MU_OFF  (2 * STG + 128)
#define RS_OFF  (2 * STG + 256)
#define SMEM_MASK_B  ((2 * STG + 384) * 4)    // 158208

// ---------------------------------------------------------------------------
// Device scratch
// ---------------------------------------------------------------------------
__device__ float g_h    [B_ * KP2 * N_];    // h = exp(attn), rows 150..191 zero
__device__ float g_P    [B_ * K_ * C_];
__device__ float g_Ppart[NSPLIT * B_ * K_ * C_];
__device__ float g_M2   [K_ * C_];
__device__ float g_clsT [K_ * C_];          // tf32-rounded cls
__device__ float g_aclsT[B_ * K_ * C_];     // tf32-rounded aligned_cls
__device__ float g_STT  [B_ * K_ * KP2];    // tf32-rounded ST, col-padded
__device__ float g_rpart[B_ * 128 * KP];    // per-block partial row sums of h
__device__ float g_rinv [B_ * K_];
__device__ float g_cinv [B_ * N_];

// ---------------------------------------------------------------------------
// helpers
// ---------------------------------------------------------------------------
__device__ __forceinline__ uint32_t f2tf(float f) {
    uint32_t u;
    asm("cvt.rna.tf32.f32 %0, %1;" : "=r"(u) : "f"(f));
    return u;
}
__device__ __forceinline__ void mma8(float* c,
                                     uint32_t a0, uint32_t a1, uint32_t a2, uint32_t a3,
                                     uint32_t b0, uint32_t b1) {
    asm("mma.sync.aligned.m16n8k8.row.col.f32.tf32.tf32.f32 "
        "{%0,%1,%2,%3}, {%4,%5,%6,%7}, {%8,%9}, {%0,%1,%2,%3};"
        : "+f"(c[0]), "+f"(c[1]), "+f"(c[2]), "+f"(c[3])
        : "r"(a0), "r"(a1), "r"(a2), "r"(a3), "r"(b0), "r"(b1));
}
__device__ __forceinline__ void cpa16(uint32_t* smem, const float* gmem) {
    uint32_t s = (uint32_t)__cvta_generic_to_shared(smem);
    asm volatile("cp.async.cg.shared.global [%0], [%1], 16;" :: "r"(s), "l"(gmem));
}
#define CPA_COMMIT asm volatile("cp.async.commit_group;")
#define CPA_WAIT0  asm volatile("cp.async.wait_group 0;")

// ---------------------------------------------------------------------------
// k_attn: h[b][k][n] = exp( sum_c cls[k][c]*x[b][c][n] ), plus per-block row
// partial sums and per-pixel col-sum inverses. m=pixel(128), n=class(160).
// 512 threads, warps 4(m) x 4(n); acc[2][5][4]. grid (N_/BM, 1, B_).
// BK=64, single-sync double-buffer.
// ---------------------------------------------------------------------------
__global__ __launch_bounds__(512, 1) void k_attn(
    const float* __restrict__ x, const float* __restrict__ clsT,
    float* __restrict__ h, float* __restrict__ rpart, float* __restrict__ cinv)
{
    extern __shared__ uint32_t sm[];
    float* Cs = (float*)sm;

    const int tid = threadIdx.x, lane = tid & 31, warp = tid >> 5;
    const int wm = (warp & 3) * 32, wn = (warp >> 2) * 40;
    const int m0 = blockIdx.x * BM;
    const int b  = blockIdx.z;
    const float* Xb = x + (long)b * C_ * N_;

    // zero Bs rows 150..159 in both stages (never written by cp.async)
    for (int i = tid; i < 2 * 10 * BKp; i += 512) {
        int s = i / (10 * BKp), rem = i % (10 * BKp);
        sm[s * STG + ABOFF + (150 + rem / BKp) * BKp + rem % BKp] = 0;
    }

    auto issue = [&](int kt, int st) {
        uint32_t* As = sm + st * STG;
        uint32_t* Bs = As + ABOFF;
        const int k0 = kt * BK;
        #pragma unroll
        for (int p = 0; p < 4; p++) {                   // As[k][m] <- x raw
            int slot = tid + p * 512;
            int r = slot >> 5, c = slot & 31;
            cpa16(As + r * BMp + c * 4, Xb + (long)(k0 + r) * N_ + m0 + c * 4);
        }
        #pragma unroll
        for (int p = 0; p < 5; p++) {                   // Bs[n][k] <- clsT
            int slot = tid + p * 512;
            if (slot < K_ * 16) {
                int r = slot >> 4, c = slot & 15;
                cpa16(Bs + r * BKp + c * 4, clsT + (long)r * C_ + k0 + c * 4);
            }
        }
        CPA_COMMIT;
    };

    issue(0, 0);
    float acc[2][5][4] = {};
    const int KT = C_ / BK;                             // 8
    for (int kt = 0; kt < KT; kt++) {
        const int cur = kt & 1;
        CPA_WAIT0;
        __syncthreads();
        if (kt + 1 < KT) issue(kt + 1, cur ^ 1);
        uint32_t* As = sm + cur * STG;
        uint32_t* Bs = As + ABOFF;
        #pragma unroll
        for (int ks = 0; ks < 8; ks++) {
            uint32_t a[2][4], bb[5][2];
            const int kc = ks * 8 + (lane & 3);
            #pragma unroll
            for (int mi = 0; mi < 2; mi++) {
                int mr = wm + mi * 16 + (lane >> 2);
                a[mi][0] = As[kc * BMp + mr];       a[mi][1] = As[kc * BMp + mr + 8];
                a[mi][2] = As[(kc + 4) * BMp + mr]; a[mi][3] = As[(kc + 4) * BMp + mr + 8];
            }
            #pragma unroll
            for (int ni = 0; ni < 5; ni++) {
                int nc = wn + ni * 8 + (lane >> 2);
                bb[ni][0] = Bs[nc * BKp + kc]; bb[ni][1] = Bs[nc * BKp + kc + 4];
            }
            #pragma unroll
            for (int mi = 0; mi < 2; mi++)
                #pragma unroll
                for (int ni = 0; ni < 5; ni++)
                    mma8(acc[mi][ni], a[mi][0], a[mi][1], a[mi][2], a[mi][3],
                         bb[ni][0], bb[ni][1]);
        }
    }
    __syncthreads();

    // stage h = exp(acc) into Cs[class][pixel]
    #pragma unroll
    for (int mi = 0; mi < 2; mi++)
        #pragma unroll
        for (int ni = 0; ni < 5; ni++) {
            int mr = wm + mi * 16 + (lane >> 2);
            int nc = wn + ni * 8 + (lane & 3) * 2;
            Cs[ nc      * BMp + mr    ] = expf(acc[mi][ni][0]);
            Cs[(nc + 1) * BMp + mr    ] = expf(acc[mi][ni][1]);
            Cs[ nc      * BMp + mr + 8] = expf(acc[mi][ni][2]);
            Cs[(nc + 1) * BMp + mr + 8] = expf(acc[mi][ni][3]);
        }
    __syncthreads();

    float* Hb = h + (long)b * KP2 * N_;
    #pragma unroll
    for (int i = 0; i < 10; i++) {
        int r = warp + i * 16;
        if (r < K_) {
            float4 v = *(float4*)(Cs + r * BMp + lane * 4);
            *(float4*)(Hb + (long)r * N_ + m0 + lane * 4) = v;
            float s = v.x + v.y + v.z + v.w;
            #pragma unroll
            for (int o = 16; o > 0; o >>= 1) s += __shfl_xor_sync(0xffffffffu, s, o);
            if (lane == 0) rpart[((long)b * 128 + blockIdx.x) * KP + r] = s;
        }
    }
    if (tid < BM) {
        float s = 0.f;
        for (int k = 0; k < K_; k++) s += Cs[k * BMp + tid];
        cinv[(long)b * N_ + m0 + tid] = 1.f / s;
    }
}

// ---------------------------------------------------------------------------
// k2_pgemm: Ppart[split][b][k][c] = sum_{pix in chunk} h[k][pix] * x[c][pix]
// m=channel(128), n=class(160). 512 threads, warps 4(m) x 4(n); acc[2][5][4].
// grid (C_/BM=4, NSPLIT, B_). BK=64.
// ---------------------------------------------------------------------------
__global__ __launch_bounds__(512, 1) void k2_pgemm(
    const float* __restrict__ Xg, const float* __restrict__ h,
    float* __restrict__ Pp)
{
    extern __shared__ uint32_t sm[];
    float* Cs = (float*)sm;

    const int tid = threadIdx.x, lane = tid & 31, warp = tid >> 5;
    const int wm = (warp & 3) * 32, wn = (warp >> 2) * 40;
    const int m0 = blockIdx.x * BM;
    const int split = blockIdx.y, b = blockIdx.z;
    const float* Xb = Xg + (long)b * C_ * N_;
    const float* Hb = h  + (long)b * KP2 * N_;

    const int kbeg = split * CHUNK;
    auto issue = [&](int kt, int st) {
        uint32_t* As = sm + st * STG;
        uint32_t* Bs = As + ABOFF;
        const int k0 = kbeg + kt * BK;
        #pragma unroll
        for (int p = 0; p < 4; p++) {                   // As[m][k] <- x raw
            int slot = tid + p * 512;
            int r = slot >> 4, c = slot & 15;
            cpa16(As + r * BKp + c * 4, Xb + (long)(m0 + r) * N_ + k0 + c * 4);
        }
        #pragma unroll
        for (int p = 0; p < 5; p++) {                   // Bs[n][k] <- h (rows 0..159 valid)
            int slot = tid + p * 512;
            int r = slot >> 4, c = slot & 15;
            cpa16(Bs + r * BKp + c * 4, Hb + (long)r * N_ + k0 + c * 4);
        }
        CPA_COMMIT;
    };

    issue(0, 0);
    float acc[2][5][4] = {};
    const int KT = CHUNK / BK;                          // 16
    for (int kt = 0; kt < KT; kt++) {
        const int cur = kt & 1;
        CPA_WAIT0;
        __syncthreads();
        if (kt + 1 < KT) issue(kt + 1, cur ^ 1);
        uint32_t* As = sm + cur * STG;
        uint32_t* Bs = As + ABOFF;
        #pragma unroll
        for (int ks = 0; ks < 8; ks++) {
            uint32_t a[2][4], bb[5][2];
            const int kc = ks * 8 + (lane & 3);
            #pragma unroll
            for (int mi = 0; mi < 2; mi++) {
                int mr = wm + mi * 16 + (lane >> 2);
                a[mi][0] = As[ mr      * BKp + kc];     a[mi][1] = As[(mr + 8) * BKp + kc];
                a[mi][2] = As[ mr      * BKp + kc + 4]; a[mi][3] = As[(mr + 8) * BKp + kc + 4];
            }
            #pragma unroll
            for (int ni = 0; ni < 5; ni++) {
                int nc = wn + ni * 8 + (lane >> 2);
                bb[ni][0] = Bs[nc * BKp + kc]; bb[ni][1] = Bs[nc * BKp + kc + 4];
            }
            #pragma unroll
            for (int mi = 0; mi < 2; mi++)
                #pragma unroll
                for (int ni = 0; ni < 5; ni++)
                    mma8(acc[mi][ni], a[mi][0], a[mi][1], a[mi][2], a[mi][3],
                         bb[ni][0], bb[ni][1]);
        }
    }
    __syncthreads();

    #pragma unroll
    for (int mi = 0; mi < 2; mi++)
        #pragma unroll
        for (int ni = 0; ni < 5; ni++) {
            int mr = wm + mi * 16 + (lane >> 2);
            int nc = wn + ni * 8 + (lane & 3) * 2;
            Cs[ nc      * BMp + mr    ] = acc[mi][ni][0];
            Cs[(nc + 1) * BMp + mr    ] = acc[mi][ni][1];
            Cs[ nc      * BMp + mr + 8] = acc[mi][ni][2];
            Cs[(nc + 1) * BMp + mr + 8] = acc[mi][ni][3];
        }
    __syncthreads();

    float* Pb = Pp + ((long)split * B_ + b) * K_ * C_;
    #pragma unroll
    for (int i = 0; i < 10; i++) {
        int r = warp + i * 16;
        if (r < K_) {
            float4 v = *(float4*)(Cs + r * BMp + lane * 4);
            *(float4*)(Pb + (long)r * C_ + m0 + lane * 4) = v;
        }
    }
}

// ---------------------------------------------------------------------------
// k_masks: out = LN_k( acls·x + ST·(h·cinv) ). Unified 11-tile pipeline:
// tiles 0..7 phase0 (x vs aclsT, BK=64), 8..10 phase1 (h vs STT over KP2=192,
// cinv applied at fragment load). 512 threads. grid (N_/BM, 1, B_)
// ---------------------------------------------------------------------------
__global__ __launch_bounds__(512, 1) void k_masks(
    const float* __restrict__ x, const float* __restrict__ aclsT,
    const float* __restrict__ STT, const float* __restrict__ h,
    const float* __restrict__ cinv,
    const float* __restrict__ gamma, const float* __restrict__ beta,
    float* __restrict__ out)
{
    extern __shared__ uint32_t sm[];
    float* Cs   = (float*)sm;
    float* ci_s = (float*)(sm + CI_OFF);
    float* mu_s = (float*)(sm + MU_OFF);
    float* rs_s = (float*)(sm + RS_OFF);

    const int tid = threadIdx.x, lane = tid & 31, warp = tid >> 5;
    const int wm = (warp & 3) * 32, wn = (warp >> 2) * 40;
    const int m0 = blockIdx.x * BM;
    const int b  = blockIdx.z;

    const float* Xb = x     + (long)b * C_ * N_;
    const float* Ab = aclsT + (long)b * K_ * C_;
    const float* Sb = STT   + (long)b * K_ * KP2;
    const float* Hb = h     + (long)b * KP2 * N_;

    if (tid < BM) ci_s[tid] = cinv[(long)b * N_ + m0 + tid];
    for (int i = tid; i < 2 * 10 * BKp; i += 512) {
        int s = i / (10 * BKp), rem = i % (10 * BKp);
        sm[s * STG + ABOFF + (150 + rem / BKp) * BKp + rem % BKp] = 0;
    }

    auto issue = [&](int kt, int st) {
        uint32_t* As = sm + st * STG;
        uint32_t* Bs = As + ABOFF;
        if (kt < 8) {
            const int k0 = kt * BK;
            #pragma unroll
            for (int p = 0; p < 4; p++) {
                int slot = tid + p * 512;
                int r = slot >> 5, c = slot & 31;
                cpa16(As + r * BMp + c * 4, Xb + (long)(k0 + r) * N_ + m0 + c * 4);
            }
            #pragma unroll
            for (int p = 0; p < 5; p++) {
                int slot = tid + p * 512;
                if (slot < K_ * 16) {
                    int r = slot >> 4, c = slot & 15;
                    cpa16(Bs + r * BKp + c * 4, Ab + (long)r * C_ + k0 + c * 4);
                }
            }
        } else {
            const int k0 = (kt - 8) * BK;
            #pragma unroll
            for (int p = 0; p < 4; p++) {               // As[k][m] <- h (rows < 192 valid)
                int slot = tid + p * 512;
                int r = slot >> 5, c = slot & 31;
                cpa16(As + r * BMp + c * 4, Hb + (long)(k0 + r) * N_ + m0 + c * 4);
            }
            #pragma unroll
            for (int p = 0; p < 5; p++) {               // Bs[n][k] <- STT (cols padded)
                int slot = tid + p * 512;
                if (slot < K_ * 16) {
                    int r = slot >> 4, c = slot & 15;
                    cpa16(Bs + r * BKp + c * 4, Sb + (long)r * KP2 + k0 + c * 4);
                }
            }
        }
        CPA_COMMIT;
    };

    issue(0, 0);
    float acc[2][5][4] = {};
    const int KT = 8 + 3;
    for (int kt = 0; kt < KT; kt++) {
        const int cur = kt & 1;
        CPA_WAIT0;
        __syncthreads();
        if (kt + 1 < KT) issue(kt + 1, cur ^ 1);
        uint32_t* As = sm + cur * STG;
        uint32_t* Bs = As + ABOFF;
        const bool ph1 = (kt >= 8);
        #pragma unroll
        for (int ks = 0; ks < 8; ks++) {
            uint32_t a[2][4], bb[5][2];
            const int kc = ks * 8 + (lane & 3);
            #pragma unroll
            for (int mi = 0; mi < 2; mi++) {
                int mr = wm + mi * 16 + (lane >> 2);
                if (!ph1) {
                    a[mi][0] = As[kc * BMp + mr];       a[mi][1] = As[kc * BMp + mr + 8];
                    a[mi][2] = As[(kc + 4) * BMp + mr]; a[mi][3] = As[(kc + 4) * BMp + mr + 8];
                } else {
                    float c0 = ci_s[mr], c1 = ci_s[mr + 8];
                    a[mi][0] = f2tf(__uint_as_float(As[kc * BMp + mr])       * c0);
                    a[mi][1] = f2tf(__uint_as_float(As[kc * BMp + mr + 8])   * c1);
                    a[mi][2] = f2tf(__uint_as_float(As[(kc + 4) * BMp + mr])     * c0);
                    a[mi][3] = f2tf(__uint_as_float(As[(kc + 4) * BMp + mr + 8]) * c1);
                }
            }
            #pragma unroll
            for (int ni = 0; ni < 5; ni++) {
                int nc = wn + ni * 8 + (lane >> 2);
                bb[ni][0] = Bs[nc * BKp + kc]; bb[ni][1] = Bs[nc * BKp + kc + 4];
            }
            #pragma unroll
            for (int mi = 0; mi < 2; mi++)
                #pragma unroll
                for (int ni = 0; ni < 5; ni++)
                    mma8(acc[mi][ni], a[mi][0], a[mi][1], a[mi][2], a[mi][3],
                         bb[ni][0], bb[ni][1]);
        }
    }
    __syncthreads();

    // stage, LayerNorm over k, write out
    #pragma unroll
    for (int mi = 0; mi < 2; mi++)
        #pragma unroll
        for (int ni = 0; ni < 5; ni++) {
            int mr = wm + mi * 16 + (lane >> 2);
            int nc = wn + ni * 8 + (lane & 3) * 2;
            Cs[ nc      * BMp + mr    ] = acc[mi][ni][0];
            Cs[(nc + 1) * BMp + mr    ] = acc[mi][ni][1];
            Cs[ nc      * BMp + mr + 8] = acc[mi][ni][2];
            Cs[(nc + 1) * BMp + mr + 8] = acc[mi][ni][3];
        }
    __syncthreads();

    if (tid < BM) {
        float s = 0.f, s2 = 0.f;
        for (int k = 0; k < K_; k++) {
            float v = Cs[k * BMp + tid];
            s += v; s2 += v * v;
        }
        float mu  = s * (1.f / K_);
        float var = s2 * (1.f / K_) - mu * mu;
        mu_s[tid] = mu;
        rs_s[tid] = rsqrtf(fmaxf(var, 0.f) + 1e-5f);
    }
    __syncthreads();

    float* Ob = out + (long)b * K_ * N_;
    #pragma unroll
    for (int i = 0; i < 10; i++) {
        int r = warp + i * 16;
        if (r < K_) {
            float g  = __ldg(&gamma[r]);
            float bt = __ldg(&beta[r]);
            int ml = lane * 4;
            float4 v = *(float4*)(Cs + r * BMp + ml);
            v.x = (v.x - mu_s[ml    ]) * rs_s[ml    ] * g + bt;
            v.y = (v.y - mu_s[ml + 1]) * rs_s[ml + 1] * g + bt;
            v.z = (v.z - mu_s[ml + 2]) * rs_s[ml + 2] * g + bt;
            v.w = (v.w - mu_s[ml + 3]) * rs_s[ml + 3] * g + bt;
            *(float4*)(Ob + (long)r * N_ + m0 + ml) = v;
        }
    }
}

// ---------------------------------------------------------------------------
// small kernels
// ---------------------------------------------------------------------------
__global__ void reduce_rinv(const float* __restrict__ rpart, float* __restrict__ rinv)
{
    int idx = blockIdx.x * blockDim.x + threadIdx.x;
    if (idx < B_ * K_) {
        int b = idx / K_, k = idx % K_;
        float s = 0.f;
        for (int blk = 0; blk < 128; blk++)
            s += rpart[((long)b * 128 + blk) * KP + k];
        rinv[idx] = 1.f / s;
    }
}

__global__ void reduce_P(const float* __restrict__ Pp, const float* __restrict__ rinv,
                         float* __restrict__ P)
{
    int i = blockIdx.x * blockDim.x + threadIdx.x;
    if (i < B_ * K_ * C_) {
        int b = i / (K_ * C_);
        int k = (i / C_) % K_;
        float s = 0.f;
        #pragma unroll
        for (int sp = 0; sp < NSPLIT; sp++) s += Pp[(long)sp * B_ * K_ * C_ + i];
        P[i] = s * rinv[b * K_ + k];
    }
}

__global__ void conv_tf32(const float* __restrict__ in, float* __restrict__ out, int n)
{
    int i = blockIdx.x * blockDim.x + threadIdx.x;
    if (i < n) out[i] = __uint_as_float(f2tf(in[i]));
}

__global__ void zero_hpad(float* __restrict__ h)
{
    int i = blockIdx.x * blockDim.x + threadIdx.x;
    int tot = B_ * (KP2 - K_) * N_;
    if (i < tot) {
        int b = i / ((KP2 - K_) * N_);
        int rem = i % ((KP2 - K_) * N_);
        h[(long)b * KP2 * N_ + (long)K_ * N_ + rem] = 0.f;
    }
}

// plain SIMT NT GEMM (used for M2 = cls @ W_feat^T)
__global__ void gemm_nt(const float* __restrict__ A, int lda,
                        const float* __restrict__ Bm, int ldb,
                        float* __restrict__ Cm, int ldc,
                        int M, int N, int Kin)
{
    __shared__ float As[16][65];
    __shared__ float Bs[16][65];
    int m0 = blockIdx.y * 64, n0 = blockIdx.x * 64;
    int tid = threadIdx.x;
    int tx = tid & 15, ty = tid >> 4;
    float acc[4][4] = {};

    for (int k0 = 0; k0 < Kin; k0 += 16) {
        #pragma unroll
        for (int j = 0; j < 4; j++) {
            int i = tid + j * 256;
            int m = i >> 4, k = i & 15;
            float v = 0.f;
            if (m0 + m < M && k0 + k < Kin) v = A[(long)(m0 + m) * lda + k0 + k];
            As[k][m] = v;
        }
        #pragma unroll
        for (int j = 0; j < 4; j++) {
            int i = tid + j * 256;
            int n = i >> 4, k = i & 15;
            float v = 0.f;
            if (n0 + n < N && k0 + k < Kin) v = Bm[(long)(n0 + n) * ldb + k0 + k];
            Bs[k][n] = v;
        }
        __syncthreads();
        #pragma unroll
        for (int kk = 0; kk < 16; kk++) {
            float a[4], bv[4];
            #pragma unroll
            for (int i = 0; i < 4; i++) a[i] = As[kk][ty + 16 * i];
            #pragma unroll
            for (int j = 0; j < 4; j++) bv[j] = Bs[kk][tx + 16 * j];
            #pragma unroll
            for (int i = 0; i < 4; i++)
                #pragma unroll
                for (int j = 0; j < 4; j++)
                    acc[i][j] += a[i] * bv[j];
        }
        __syncthreads();
    }

    #pragma unroll
    for (int i = 0; i < 4; i++) {
        int m = m0 + ty + 16 * i;
        if (m >= M) continue;
        #pragma unroll
        for (int j = 0; j < 4; j++) {
            int n = n0 + tx + 16 * j;
            if (n >= N) continue;
            Cm[(long)m * ldc + n] = acc[i][j];
        }
    }
}

// gemm_acls: aclsT[b] = tf32( cls + P[b] @ W_cls^T ). grid (8, 3, B_)
__global__ void gemm_acls(const float* __restrict__ P, const float* __restrict__ Wc,
                          const float* __restrict__ cls, float* __restrict__ aclsT)
{
    __shared__ float As[16][65];
    __shared__ float Bs[16][65];
    const float* Ab = P + (long)blockIdx.z * K_ * C_;
    float*       Cb = aclsT + (long)blockIdx.z * K_ * C_;
    int m0 = blockIdx.y * 64, n0 = blockIdx.x * 64;
    int tid = threadIdx.x;
    int tx = tid & 15, ty = tid >> 4;
    float acc[4][4] = {};

    for (int k0 = 0; k0 < C_; k0 += 16) {
        #pragma unroll
        for (int j = 0; j < 4; j++) {
            int i = tid + j * 256;
            int m = i >> 4, k = i & 15;
            float v = 0.f;
            if (m0 + m < K_) v = Ab[(long)(m0 + m) * C_ + k0 + k];
            As[k][m] = v;
        }
        #pragma unroll
        for (int j = 0; j < 4; j++) {
            int i = tid + j * 256;
            int n = i >> 4, k = i & 15;
            Bs[k][n] = Wc[(long)(n0 + n) * C_ + k0 + k];
        }
        __syncthreads();
        #pragma unroll
        for (int kk = 0; kk < 16; kk++) {
            float a[4], bv[4];
            #pragma unroll
            for (int i = 0; i < 4; i++) a[i] = As[kk][ty + 16 * i];
            #pragma unroll
            for (int j = 0; j < 4; j++) bv[j] = Bs[kk][tx + 16 * j];
            #pragma unroll
            for (int i = 0; i < 4; i++)
                #pragma unroll
                for (int j = 0; j < 4; j++)
                    acc[i][j] += a[i] * bv[j];
        }
        __syncthreads();
    }

    #pragma unroll
    for (int i = 0; i < 4; i++) {
        int m = m0 + ty + 16 * i;
        if (m >= K_) continue;
        #pragma unroll
        for (int j = 0; j < 4; j++) {
            int n = n0 + tx + 16 * j;
            float v = acc[i][j] + cls[(long)m * C_ + n];
            Cb[(long)m * C_ + n] = __uint_as_float(f2tf(v));
        }
    }
}

// gemm_STT: STT[b][k'][k] = tf32( sum_d aclsT[b][k'][d] * M2[k][d] ), cols
// padded to KP2 with zeros. grid (3, 3, B_)  (covers 192x192)
__global__ void gemm_STT(const float* __restrict__ aclsT, const float* __restrict__ M2,
                         float* __restrict__ STT)
{
    __shared__ float As[16][65];
    __shared__ float Bs[16][65];
    const float* Ab = aclsT + (long)blockIdx.z * K_ * C_;
    float*       Cb = STT   + (long)blockIdx.z * K_ * KP2;
    int m0 = blockIdx.y * 64, n0 = blockIdx.x * 64;
    int tid = threadIdx.x;
    int tx = tid & 15, ty = tid >> 4;
    float acc[4][4] = {};

    for (int k0 = 0; k0 < C_; k0 += 16) {
        #pragma unroll
        for (int j = 0; j < 4; j++) {
            int i = tid + j * 256;
            int m = i >> 4, k = i & 15;
            float v = 0.f;
            if (m0 + m < K_) v = Ab[(long)(m0 + m) * C_ + k0 + k];
            As[k][m] = v;
        }
        #pragma unroll
        for (int j = 0; j < 4; j++) {
            int i = tid + j * 256;
            int n = i >> 4, k = i & 15;
            float v = 0.f;
            if (n0 + n < K_) v = M2[(long)(n0 + n) * C_ + k0 + k];
            Bs[k][n] = v;
        }
        __syncthreads();
        #pragma unroll
        for (int kk = 0; kk < 16; kk++) {
            float a[4], bv[4];
            #pragma unroll
            for (int i = 0; i < 4; i++) a[i] = As[kk][ty + 16 * i];
            #pragma unroll
            for (int j = 0; j < 4; j++) bv[j] = Bs[kk][tx + 16 * j];
            #pragma unroll
            for (int i = 0; i < 4; i++)
                #pragma unroll
                for (int j = 0; j < 4; j++)
                    acc[i][j] += a[i] * bv[j];
        }
        __syncthreads();
    }

    #pragma unroll
    for (int i = 0; i < 4; i++) {
        int m = m0 + ty + 16 * i;
        if (m >= K_) continue;
        #pragma unroll
        for (int j = 0; j < 4; j++) {
            int n = n0 + tx + 16 * j;
            if (n >= KP2) continue;
            float v = (n < K_) ? __uint_as_float(f2tf(acc[i][j])) : 0.f;
            Cb[(long)m * KP2 + n] = v;
        }
    }
}

// ---------------------------------------------------------------------------
// kernel_launch
// ---------------------------------------------------------------------------
extern "C" void kernel_launch(void* const* d_in, const int* in_sizes, int n_in,
                              void* d_out, int out_size)
{
    const float* x      = (const float*)d_in[0];
    const float* cls    = (const float*)d_in[1];
    const float* W_cls  = (const float*)d_in[2];
    const float* W_feat = (const float*)d_in[3];
    const float* gamma  = (const float*)d_in[4];
    const float* beta   = (const float*)d_in[5];
    float* out = (float*)d_out;

    float *h, *P, *Ppart, *M2, *clsT, *aclsT, *STT, *rpart, *rinv, *cinv;
    cudaGetSymbolAddress((void**)&h,     g_h);
    cudaGetSymbolAddress((void**)&P,     g_P);
    cudaGetSymbolAddress((void**)&Ppart, g_Ppart);
    cudaGetSymbolAddress((void**)&M2,    g_M2);
    cudaGetSymbolAddress((void**)&clsT,  g_clsT);
    cudaGetSymbolAddress((void**)&aclsT, g_aclsT);
    cudaGetSymbolAddress((void**)&STT,   g_STT);
    cudaGetSymbolAddress((void**)&rpart, g_rpart);
    cudaGetSymbolAddress((void**)&rinv,  g_rinv);
    cudaGetSymbolAddress((void**)&cinv,  g_cinv);

    cudaFuncSetAttribute(k_attn,  cudaFuncAttributeMaxDynamicSharedMemorySize, SMEM_GEMM_B);
    cudaFuncSetAttribute(k2_pgemm, cudaFuncAttributeMaxDynamicSharedMemorySize, SMEM_GEMM_B);
    cudaFuncSetAttribute(k_masks, cudaFuncAttributeMaxDynamicSharedMemorySize, SMEM_MASK_B);

    // prep: tf32 cls, zero h padding, M2 = cls @ W_feat^T
    conv_tf32<<<(K_ * C_ + 255) / 256, 256>>>(cls, clsT, K_ * C_);
    zero_hpad<<<(B_ * (KP2 - K_) * N_ + 255) / 256, 256>>>(h);
    gemm_nt<<<dim3(8, 3, 1), 256>>>(cls, C_, W_feat, C_, M2, C_, K_, C_, C_);

    // h = exp(attn) + row partials + col inverses
    k_attn<<<dim3(N_ / BM, 1, B_), 512, SMEM_GEMM_B>>>(x, clsT, h, rpart, cinv);
    reduce_rinv<<<(B_ * K_ + 255) / 256, 256>>>(rpart, rinv);

    // P = rowsoftmax @ img_feat  (unnormalized in k2, scaled in reduce)
    k2_pgemm<<<dim3(C_ / BM, NSPLIT, B_), 512, SMEM_GEMM_B>>>(x, h, Ppart);
    reduce_P<<<(B_ * K_ * C_ + 255) / 256, 256>>>(Ppart, rinv, P);

    // aclsT = tf32(cls + P @ W_cls^T); STT = tf32(aclsT @ M2^T) padded
    gemm_acls<<<dim3(8, 3, B_), 256>>>(P, W_cls, cls, aclsT);
    gemm_STT<<<dim3(3, 3, B_), 256>>>(aclsT, M2, STT);

    // out = LN( acls·x + ST·(h·cinv) )
    k_masks<<<dim3(N_ / BM, 1, B_), 512, SMEM_MASK_B>>>(
        x, aclsT, STT, h, cinv, gamma, beta, out);
}

// round 12
// speedup vs baseline: 1.0927x; 1.0927x over previous
#include <cuda_runtime.h>
#include <cuda_fp16.h>
#include <cstdint>

// Problem constants
#define B_  8
#define C_  512          // channels == D
#define N_  16384        // H*W
#define K_  150          // num classes
#define KP  160          // K padded
#define NSPLIT 8
#define CHUNK (N_ / NSPLIT)   // 2048

// Tile config
#define BM  128
#define BN  160
#define BK  32
#define BMp 136   // pad: conflict-free [k][m] frag reads
#define BKp 36    // pad: conflict-free [n][k] frag reads (fp32)
#define BKh 40    // fp16 [n][k] row pad (halves)

// stage sizes (words)
#define STG_A (32 * BMp + BN * BKp)    // k_attn / k_masks: 10112
#define STG_2 (BM * BKp + BN * BKh / 2) // k2: 4608 + 3200 = 7808
#define AB2   (BM * BKp)               // k2 Bs offset (words)
#define CS_W  (BN * BMp)               // 21760

#define SMEM_GEMM_B  (CS_W * 4)               // 87040 (Cs dominates stages)
#define CI_OFF  CS_W
#define MU_OFF  (CS_W + 128)
#define RS_OFF  (CS_W + 256)
#define SMEM_MASK_B  ((CS_W + 384) * 4)       // 88576

// ---------------------------------------------------------------------------
// Device scratch
// ---------------------------------------------------------------------------
__device__ __half g_h2  [B_ * KP * N_];     // h = exp(attn) fp16, rows 150..159 zero
__device__ float  g_P   [B_ * K_ * C_];
__device__ float  g_Ppart[NSPLIT * B_ * K_ * C_];
__device__ float  g_M2  [K_ * C_];
__device__ float  g_clsT[K_ * C_];          // tf32-rounded cls
__device__ float  g_aclsT[B_ * K_ * C_];    // tf32-rounded aligned_cls
__device__ __half g_STT2[B_ * K_ * KP];     // fp16 ST, col-padded (zeros >=150)
__device__ float  g_rpart[B_ * 128 * KP];
__device__ float  g_rinv[B_ * K_];
__device__ float  g_cinv[B_ * N_];

// ---------------------------------------------------------------------------
// helpers
// ---------------------------------------------------------------------------
__device__ __forceinline__ uint32_t f2tf(float f) {
    uint32_t u;
    asm("cvt.rna.tf32.f32 %0, %1;" : "=r"(u) : "f"(f));
    return u;
}
__device__ __forceinline__ void mma8(float* c,
                                     uint32_t a0, uint32_t a1, uint32_t a2, uint32_t a3,
                                     uint32_t b0, uint32_t b1) {
    asm("mma.sync.aligned.m16n8k8.row.col.f32.tf32.tf32.f32 "
        "{%0,%1,%2,%3}, {%4,%5,%6,%7}, {%8,%9}, {%0,%1,%2,%3};"
        : "+f"(c[0]), "+f"(c[1]), "+f"(c[2]), "+f"(c[3])
        : "r"(a0), "r"(a1), "r"(a2), "r"(a3), "r"(b0), "r"(b1));
}
__device__ __forceinline__ void cpa16(const void* smem, const void* gmem) {
    uint32_t s = (uint32_t)__cvta_generic_to_shared(smem);
    asm volatile("cp.async.cg.shared.global [%0], [%1], 16;" :: "r"(s), "l"(gmem));
}
#define CPA_COMMIT asm volatile("cp.async.commit_group;")
#define CPA_WAIT0  asm volatile("cp.async.wait_group 0;")

// ---------------------------------------------------------------------------
// k_attn: h2[b][k][n] = fp16(exp( sum_c cls[k][c]*x[b][c][n] )), plus per-block
// row partial sums and per-pixel col-sum inverses. m=pixel(128), n=class(160).
// 256 threads, warps 4(m) x 2(n); acc[2][10][4]. grid (N_/BM, 1, B_).
// Pad class-rows 150..159 are stale garbage -> outputs discarded (r<K_ guards).
// ---------------------------------------------------------------------------
__global__ __launch_bounds__(256, 2) void k_attn(
    const float* __restrict__ x, const float* __restrict__ clsT,
    __half* __restrict__ h2, float* __restrict__ rpart, float* __restrict__ cinv)
{
    extern __shared__ uint32_t sm[];
    float* Cs = (float*)sm;

    const int tid = threadIdx.x, lane = tid & 31, warp = tid >> 5;
    const int wm = (warp & 3) * 32, wn = (warp >> 2) * 80;
    const int m0 = blockIdx.x * BM;
    const int b  = blockIdx.z;
    const float* Xb = x + (long)b * C_ * N_;

    auto issue = [&](int kt, int st) {
        uint32_t* As = sm + st * STG_A;
        uint32_t* Bs = As + 32 * BMp;
        const int k0 = kt * BK;
        #pragma unroll
        for (int p = 0; p < 4; p++) {                   // As[k][m] <- x raw
            int slot = tid + p * 256;
            int r = slot >> 5, c = slot & 31;
            cpa16(As + r * BMp + c * 4, Xb + (long)(k0 + r) * N_ + m0 + c * 4);
        }
        #pragma unroll
        for (int p = 0; p < 5; p++) {                   // Bs[n][k] <- clsT
            int slot = tid + p * 256;
            if (slot < K_ * 8) {
                int r = slot >> 3, c = slot & 7;
                cpa16(Bs + r * BKp + c * 4, clsT + (long)r * C_ + k0 + c * 4);
            }
        }
        CPA_COMMIT;
    };

    issue(0, 0);
    float acc[2][10][4] = {};
    const int KT = C_ / BK;                             // 16
    for (int kt = 0; kt < KT; kt++) {
        const int cur = kt & 1;
        CPA_WAIT0;
        __syncthreads();
        if (kt + 1 < KT) issue(kt + 1, cur ^ 1);
        uint32_t* As = sm + cur * STG_A;
        uint32_t* Bs = As + 32 * BMp;
        #pragma unroll
        for (int ks = 0; ks < 4; ks++) {
            uint32_t a[2][4], bb[10][2];
            const int kc = ks * 8 + (lane & 3);
            #pragma unroll
            for (int mi = 0; mi < 2; mi++) {
                int mr = wm + mi * 16 + (lane >> 2);
                a[mi][0] = As[kc * BMp + mr];       a[mi][1] = As[kc * BMp + mr + 8];
                a[mi][2] = As[(kc + 4) * BMp + mr]; a[mi][3] = As[(kc + 4) * BMp + mr + 8];
            }
            #pragma unroll
            for (int ni = 0; ni < 10; ni++) {
                int nc = wn + ni * 8 + (lane >> 2);
                bb[ni][0] = Bs[nc * BKp + kc]; bb[ni][1] = Bs[nc * BKp + kc + 4];
            }
            #pragma unroll
            for (int mi = 0; mi < 2; mi++)
                #pragma unroll
                for (int ni = 0; ni < 10; ni++)
                    mma8(acc[mi][ni], a[mi][0], a[mi][1], a[mi][2], a[mi][3],
                         bb[ni][0], bb[ni][1]);
        }
    }
    __syncthreads();

    // stage h = exp(acc) into Cs[class][pixel]
    #pragma unroll
    for (int mi = 0; mi < 2; mi++)
        #pragma unroll
        for (int ni = 0; ni < 10; ni++) {
            int mr = wm + mi * 16 + (lane >> 2);
            int nc = wn + ni * 8 + (lane & 3) * 2;
            Cs[ nc      * BMp + mr    ] = expf(acc[mi][ni][0]);
            Cs[(nc + 1) * BMp + mr    ] = expf(acc[mi][ni][1]);
            Cs[ nc      * BMp + mr + 8] = expf(acc[mi][ni][2]);
            Cs[(nc + 1) * BMp + mr + 8] = expf(acc[mi][ni][3]);
        }
    __syncthreads();

    __half* Hb2 = h2 + (long)b * KP * N_;
    #pragma unroll
    for (int i = 0; i < 19; i++) {
        int r = warp + i * 8;
        if (r < K_) {
            float4 v = *(float4*)(Cs + r * BMp + lane * 4);
            __half2 p0 = __floats2half2_rn(v.x, v.y);
            __half2 p1 = __floats2half2_rn(v.z, v.w);
            uint2 st = make_uint2(*(uint32_t*)&p0, *(uint32_t*)&p1);
            *(uint2*)(Hb2 + (long)r * N_ + m0 + lane * 4) = st;
            float s = v.x + v.y + v.z + v.w;
            #pragma unroll
            for (int o = 16; o > 0; o >>= 1) s += __shfl_xor_sync(0xffffffffu, s, o);
            if (lane == 0) rpart[((long)b * 128 + blockIdx.x) * KP + r] = s;
        }
    }
    if (tid < BM) {
        float s = 0.f;
        for (int k = 0; k < K_; k++) s += Cs[k * BMp + tid];
        cinv[(long)b * N_ + m0 + tid] = 1.f / s;
    }
}

// ---------------------------------------------------------------------------
// k2_pgemm: Ppart[split][b][k][c] = sum_{pix in chunk} h2[k][pix] * x[c][pix]
// m=channel, n=class. B-side fp16 (smem halves, converted at fragment load).
// warps 2(m) x 4(n); acc[4][5][4]. grid (C_/BM=4, NSPLIT, B_).
// ---------------------------------------------------------------------------
__global__ __launch_bounds__(256, 2) void k2_pgemm(
    const float* __restrict__ Xg, const __half* __restrict__ h2,
    float* __restrict__ Pp)
{
    extern __shared__ uint32_t sm[];
    float* Cs = (float*)sm;

    const int tid = threadIdx.x, lane = tid & 31, warp = tid >> 5;
    const int wm = (warp & 1) * 64, wn = (warp >> 1) * 40;
    const int m0 = blockIdx.x * BM;
    const int split = blockIdx.y, b = blockIdx.z;
    const float* Xb  = Xg + (long)b * C_ * N_;
    const __half* Hb = h2 + (long)b * KP * N_;

    const int kbeg = split * CHUNK;
    auto issue = [&](int kt, int st) {
        uint32_t* As  = sm + st * STG_2;
        __half*  Bs16 = (__half*)(As + AB2);
        const int k0 = kbeg + kt * BK;
        #pragma unroll
        for (int p = 0; p < 4; p++) {                   // As[m][k] <- x raw
            int slot = tid + p * 256;
            int r = slot >> 3, c = slot & 7;
            cpa16(As + r * BKp + c * 4, Xb + (long)(m0 + r) * N_ + k0 + c * 4);
        }
        #pragma unroll
        for (int p = 0; p < 3; p++) {                   // Bs16[n][k] <- h2 (rows 0..159)
            int slot = tid + p * 256;
            if (slot < KP * 4) {
                int r = slot >> 2, c = slot & 3;
                cpa16(Bs16 + r * BKh + c * 8, Hb + (long)r * N_ + k0 + c * 8);
            }
        }
        CPA_COMMIT;
    };

    issue(0, 0);
    float acc[4][5][4] = {};
    const int KT = CHUNK / BK;                          // 64
    for (int kt = 0; kt < KT; kt++) {
        const int cur = kt & 1;
        CPA_WAIT0;
        __syncthreads();
        if (kt + 1 < KT) issue(kt + 1, cur ^ 1);
        uint32_t* As  = sm + cur * STG_2;
        __half*  Bs16 = (__half*)(As + AB2);
        #pragma unroll
        for (int ks = 0; ks < 4; ks++) {
            uint32_t a[4][4], bb[5][2];
            const int kc = ks * 8 + (lane & 3);
            #pragma unroll
            for (int mi = 0; mi < 4; mi++) {
                int mr = wm + mi * 16 + (lane >> 2);
                a[mi][0] = As[ mr      * BKp + kc];     a[mi][1] = As[(mr + 8) * BKp + kc];
                a[mi][2] = As[ mr      * BKp + kc + 4]; a[mi][3] = As[(mr + 8) * BKp + kc + 4];
            }
            #pragma unroll
            for (int ni = 0; ni < 5; ni++) {
                int nc = wn + ni * 8 + (lane >> 2);
                bb[ni][0] = f2tf(__half2float(Bs16[nc * BKh + kc]));
                bb[ni][1] = f2tf(__half2float(Bs16[nc * BKh + kc + 4]));
            }
            #pragma unroll
            for (int mi = 0; mi < 4; mi++)
                #pragma unroll
                for (int ni = 0; ni < 5; ni++)
                    mma8(acc[mi][ni], a[mi][0], a[mi][1], a[mi][2], a[mi][3],
                         bb[ni][0], bb[ni][1]);
        }
    }
    __syncthreads();

    #pragma unroll
    for (int mi = 0; mi < 4; mi++)
        #pragma unroll
        for (int ni = 0; ni < 5; ni++) {
            int mr = wm + mi * 16 + (lane >> 2);
            int nc = wn + ni * 8 + (lane & 3) * 2;
            Cs[ nc      * BMp + mr    ] = acc[mi][ni][0];
            Cs[(nc + 1) * BMp + mr    ] = acc[mi][ni][1];
            Cs[ nc      * BMp + mr + 8] = acc[mi][ni][2];
            Cs[(nc + 1) * BMp + mr + 8] = acc[mi][ni][3];
        }
    __syncthreads();

    float* Pb = Pp + ((long)split * B_ + b) * K_ * C_;
    #pragma unroll
    for (int i = 0; i < 19; i++) {
        int r = warp + i * 8;
        if (r < K_) {
            float4 v = *(float4*)(Cs + r * BMp + lane * 4);
            *(float4*)(Pb + (long)r * C_ + m0 + lane * 4) = v;
        }
    }
}

// ---------------------------------------------------------------------------
// k_masks: out = LN_k( acls·x + ST·(h·cinv) ). 21-tile pipeline: tiles 0..15
// phase0 (x fp32 vs aclsT), 16..20 phase1 (h2 fp16 vs STT2 fp16, cinv applied
// at fragment load). grid (N_/BM, 1, B_)
// ---------------------------------------------------------------------------
__global__ __launch_bounds__(256, 2) void k_masks(
    const float* __restrict__ x, const float* __restrict__ aclsT,
    const __half* __restrict__ STT2, const __half* __restrict__ h2,
    const float* __restrict__ cinv,
    const float* __restrict__ gamma, const float* __restrict__ beta,
    float* __restrict__ out)
{
    extern __shared__ uint32_t sm[];
    float* Cs   = (float*)sm;
    float* ci_s = (float*)(sm + CI_OFF);
    float* mu_s = (float*)(sm + MU_OFF);
    float* rs_s = (float*)(sm + RS_OFF);

    const int tid = threadIdx.x, lane = tid & 31, warp = tid >> 5;
    const int wm = (warp & 3) * 32, wn = (warp >> 2) * 80;
    const int m0 = blockIdx.x * BM;
    const int b  = blockIdx.z;

    const float*  Xb  = x     + (long)b * C_ * N_;
    const float*  Ab  = aclsT + (long)b * K_ * C_;
    const __half* Sb  = STT2  + (long)b * K_ * KP;
    const __half* Hb  = h2    + (long)b * KP * N_;

    if (tid < BM) ci_s[tid] = cinv[(long)b * N_ + m0 + tid];

    auto issue = [&](int kt, int st) {
        uint32_t* As   = sm + st * STG_A;
        uint32_t* Bs   = As + 32 * BMp;
        __half*   As16 = (__half*)As;
        __half*   Bs16 = (__half*)Bs;
        if (kt < 16) {
            const int k0 = kt * BK;
            #pragma unroll
            for (int p = 0; p < 4; p++) {
                int slot = tid + p * 256;
                int r = slot >> 5, c = slot & 31;
                cpa16(As + r * BMp + c * 4, Xb + (long)(k0 + r) * N_ + m0 + c * 4);
            }
            #pragma unroll
            for (int p = 0; p < 5; p++) {
                int slot = tid + p * 256;
                if (slot < K_ * 8) {
                    int r = slot >> 3, c = slot & 7;
                    cpa16(Bs + r * BKp + c * 4, Ab + (long)r * C_ + k0 + c * 4);
                }
            }
        } else {
            const int k0 = (kt - 16) * BK;
            #pragma unroll
            for (int p = 0; p < 2; p++) {               // As16[k][m] <- h2 (rows <160)
                int slot = tid + p * 256;
                int r = slot >> 4, c = slot & 15;
                cpa16(As16 + r * BMp + c * 8, Hb + (long)(k0 + r) * N_ + m0 + c * 8);
            }
            #pragma unroll
            for (int p = 0; p < 3; p++) {               // Bs16[n][k] <- STT2 (cols pad=0)
                int slot = tid + p * 256;
                if (slot < K_ * 4) {
                    int r = slot >> 2, c = slot & 3;
                    cpa16(Bs16 + r * BKh + c * 8, Sb + (long)r * KP + k0 + c * 8);
                }
            }
        }
        CPA_COMMIT;
    };

    issue(0, 0);
    float acc[2][10][4] = {};
    const int KT = 16 + 5;
    for (int kt = 0; kt < KT; kt++) {
        const int cur = kt & 1;
        CPA_WAIT0;
        __syncthreads();
        if (kt + 1 < KT) issue(kt + 1, cur ^ 1);
        uint32_t* As   = sm + cur * STG_A;
        uint32_t* Bs   = As + 32 * BMp;
        __half*   As16 = (__half*)As;
        __half*   Bs16 = (__half*)Bs;
        const bool ph1 = (kt >= 16);
        #pragma unroll
        for (int ks = 0; ks < 4; ks++) {
            uint32_t a[2][4], bb[10][2];
            const int kc = ks * 8 + (lane & 3);
            #pragma unroll
            for (int mi = 0; mi < 2; mi++) {
                int mr = wm + mi * 16 + (lane >> 2);
                if (!ph1) {
                    a[mi][0] = As[kc * BMp + mr];       a[mi][1] = As[kc * BMp + mr + 8];
                    a[mi][2] = As[(kc + 4) * BMp + mr]; a[mi][3] = As[(kc + 4) * BMp + mr + 8];
                } else {
                    float c0 = ci_s[mr], c1 = ci_s[mr + 8];
                    a[mi][0] = f2tf(__half2float(As16[kc * BMp + mr])       * c0);
                    a[mi][1] = f2tf(__half2float(As16[kc * BMp + mr + 8])   * c1);
                    a[mi][2] = f2tf(__half2float(As16[(kc + 4) * BMp + mr])     * c0);
                    a[mi][3] = f2tf(__half2float(As16[(kc + 4) * BMp + mr + 8]) * c1);
                }
            }
            #pragma unroll
            for (int ni = 0; ni < 10; ni++) {
                int nc = wn + ni * 8 + (lane >> 2);
                if (!ph1) {
                    bb[ni][0] = Bs[nc * BKp + kc]; bb[ni][1] = Bs[nc * BKp + kc + 4];
                } else {
                    bb[ni][0] = f2tf(__half2float(Bs16[nc * BKh + kc]));
                    bb[ni][1] = f2tf(__half2float(Bs16[nc * BKh + kc + 4]));
                }
            }
            #pragma unroll
            for (int mi = 0; mi < 2; mi++)
                #pragma unroll
                for (int ni = 0; ni < 10; ni++)
                    mma8(acc[mi][ni], a[mi][0], a[mi][1], a[mi][2], a[mi][3],
                         bb[ni][0], bb[ni][1]);
        }
    }
    __syncthreads();

    // stage, LayerNorm over k, write out
    #pragma unroll
    for (int mi = 0; mi < 2; mi++)
        #pragma unroll
        for (int ni = 0; ni < 10; ni++) {
            int mr = wm + mi * 16 + (lane >> 2);
            int nc = wn + ni * 8 + (lane & 3) * 2;
            Cs[ nc      * BMp + mr    ] = acc[mi][ni][0];
            Cs[(nc + 1) * BMp + mr    ] = acc[mi][ni][1];
            Cs[ nc      * BMp + mr + 8] = acc[mi][ni][2];
            Cs[(nc + 1) * BMp + mr + 8] = acc[mi][ni][3];
        }
    __syncthreads();

    if (tid < BM) {
        float s = 0.f, s2 = 0.f;
        for (int k = 0; k < K_; k++) {
            float v = Cs[k * BMp + tid];
            s += v; s2 += v * v;
        }
        float mu  = s * (1.f / K_);
        float var = s2 * (1.f / K_) - mu * mu;
        mu_s[tid] = mu;
        rs_s[tid] = rsqrtf(fmaxf(var, 0.f) + 1e-5f);
    }
    __syncthreads();

    float* Ob = out + (long)b * K_ * N_;
    #pragma unroll
    for (int i = 0; i < 19; i++) {
        int r = warp + i * 8;
        if (r < K_) {
            float g  = __ldg(&gamma[r]);
            float bt = __ldg(&beta[r]);
            int ml = lane * 4;
            float4 v = *(float4*)(Cs + r * BMp + ml);
            v.x = (v.x - mu_s[ml    ]) * rs_s[ml    ] * g + bt;
            v.y = (v.y - mu_s[ml + 1]) * rs_s[ml + 1] * g + bt;
            v.z = (v.z - mu_s[ml + 2]) * rs_s[ml + 2] * g + bt;
            v.w = (v.w - mu_s[ml + 3]) * rs_s[ml + 3] * g + bt;
            *(float4*)(Ob + (long)r * N_ + m0 + ml) = v;
        }
    }
}

// ---------------------------------------------------------------------------
// small kernels
// ---------------------------------------------------------------------------
__global__ void reduce_rinv(const float* __restrict__ rpart, float* __restrict__ rinv)
{
    int idx = blockIdx.x * blockDim.x + threadIdx.x;
    if (idx < B_ * K_) {
        int b = idx / K_, k = idx % K_;
        float s = 0.f;
        for (int blk = 0; blk < 128; blk++)
            s += rpart[((long)b * 128 + blk) * KP + k];
        rinv[idx] = 1.f / s;
    }
}

__global__ void reduce_P(const float* __restrict__ Pp, const float* __restrict__ rinv,
                         float* __restrict__ P)
{
    int i = blockIdx.x * blockDim.x + threadIdx.x;
    if (i < B_ * K_ * C_) {
        int b = i / (K_ * C_);
        int k = (i / C_) % K_;
        float s = 0.f;
        #pragma unroll
        for (int sp = 0; sp < NSPLIT; sp++) s += Pp[(long)sp * B_ * K_ * C_ + i];
        P[i] = s * rinv[b * K_ + k];
    }
}

__global__ void conv_tf32(const float* __restrict__ in, float* __restrict__ out, int n)
{
    int i = blockIdx.x * blockDim.x + threadIdx.x;
    if (i < n) out[i] = __uint_as_float(f2tf(in[i]));
}

__global__ void zero_hpad(__half* __restrict__ h2)
{
    int i = blockIdx.x * blockDim.x + threadIdx.x;
    int tot = B_ * (KP - K_) * N_;
    if (i < tot) {
        int b = i / ((KP - K_) * N_);
        int rem = i % ((KP - K_) * N_);
        h2[(long)b * KP * N_ + (long)K_ * N_ + rem] = __float2half(0.f);
    }
}

// plain SIMT NT GEMM (used for M2 = cls @ W_feat^T)
__global__ void gemm_nt(const float* __restrict__ A, int lda,
                        const float* __restrict__ Bm, int ldb,
                        float* __restrict__ Cm, int ldc,
                        int M, int N, int Kin)
{
    __shared__ float As[16][65];
    __shared__ float Bs[16][65];
    int m0 = blockIdx.y * 64, n0 = blockIdx.x * 64;
    int tid = threadIdx.x;
    int tx = tid & 15, ty = tid >> 4;
    float acc[4][4] = {};

    for (int k0 = 0; k0 < Kin; k0 += 16) {
        #pragma unroll
        for (int j = 0; j < 4; j++) {
            int i = tid + j * 256;
            int m = i >> 4, k = i & 15;
            float v = 0.f;
            if (m0 + m < M && k0 + k < Kin) v = A[(long)(m0 + m) * lda + k0 + k];
            As[k][m] = v;
        }
        #pragma unroll
        for (int j = 0; j < 4; j++) {
            int i = tid + j * 256;
            int n = i >> 4, k = i & 15;
            float v = 0.f;
            if (n0 + n < N && k0 + k < Kin) v = Bm[(long)(n0 + n) * ldb + k0 + k];
            Bs[k][n] = v;
        }
        __syncthreads();
        #pragma unroll
        for (int kk = 0; kk < 16; kk++) {
            float a[4], bv[4];
            #pragma unroll
            for (int i = 0; i < 4; i++) a[i] = As[kk][ty + 16 * i];
            #pragma unroll
            for (int j = 0; j < 4; j++) bv[j] = Bs[kk][tx + 16 * j];
            #pragma unroll
            for (int i = 0; i < 4; i++)
                #pragma unroll
                for (int j = 0; j < 4; j++)
                    acc[i][j] += a[i] * bv[j];
        }
        __syncthreads();
    }

    #pragma unroll
    for (int i = 0; i < 4; i++) {
        int m = m0 + ty + 16 * i;
        if (m >= M) continue;
        #pragma unroll
        for (int j = 0; j < 4; j++) {
            int n = n0 + tx + 16 * j;
            if (n >= N) continue;
            Cm[(long)m * ldc + n] = acc[i][j];
        }
    }
}

// gemm_acls: aclsT[b] = tf32( cls + P[b] @ W_cls^T ). grid (8, 3, B_)
__global__ void gemm_acls(const float* __restrict__ P, const float* __restrict__ Wc,
                          const float* __restrict__ cls, float* __restrict__ aclsT)
{
    __shared__ float As[16][65];
    __shared__ float Bs[16][65];
    const float* Ab = P + (long)blockIdx.z * K_ * C_;
    float*       Cb = aclsT + (long)blockIdx.z * K_ * C_;
    int m0 = blockIdx.y * 64, n0 = blockIdx.x * 64;
    int tid = threadIdx.x;
    int tx = tid & 15, ty = tid >> 4;
    float acc[4][4] = {};

    for (int k0 = 0; k0 < C_; k0 += 16) {
        #pragma unroll
        for (int j = 0; j < 4; j++) {
            int i = tid + j * 256;
            int m = i >> 4, k = i & 15;
            float v = 0.f;
            if (m0 + m < K_) v = Ab[(long)(m0 + m) * C_ + k0 + k];
            As[k][m] = v;
        }
        #pragma unroll
        for (int j = 0; j < 4; j++) {
            int i = tid + j * 256;
            int n = i >> 4, k = i & 15;
            Bs[k][n] = Wc[(long)(n0 + n) * C_ + k0 + k];
        }
        __syncthreads();
        #pragma unroll
        for (int kk = 0; kk < 16; kk++) {
            float a[4], bv[4];
            #pragma unroll
            for (int i = 0; i < 4; i++) a[i] = As[kk][ty + 16 * i];
            #pragma unroll
            for (int j = 0; j < 4; j++) bv[j] = Bs[kk][tx + 16 * j];
            #pragma unroll
            for (int i = 0; i < 4; i++)
                #pragma unroll
                for (int j = 0; j < 4; j++)
                    acc[i][j] += a[i] * bv[j];
        }
        __syncthreads();
    }

    #pragma unroll
    for (int i = 0; i < 4; i++) {
        int m = m0 + ty + 16 * i;
        if (m >= K_) continue;
        #pragma unroll
        for (int j = 0; j < 4; j++) {
            int n = n0 + tx + 16 * j;
            float v = acc[i][j] + cls[(long)m * C_ + n];
            Cb[(long)m * C_ + n] = __uint_as_float(f2tf(v));
        }
    }
}

// gemm_STT: STT2[b][k'][k] = fp16( sum_d aclsT[b][k'][d] * M2[k][d] ), cols
// padded to KP with zeros. grid (3, 3, B_)  (covers 192x192 >= 150x160)
__global__ void gemm_STT(const float* __restrict__ aclsT, const float* __restrict__ M2,
                         __half* __restrict__ STT2)
{
    __shared__ float As[16][65];
    __shared__ float Bs[16][65];
    const float* Ab = aclsT + (long)blockIdx.z * K_ * C_;
    __half*      Cb = STT2  + (long)blockIdx.z * K_ * KP;
    int m0 = blockIdx.y * 64, n0 = blockIdx.x * 64;
    int tid = threadIdx.x;
    int tx = tid & 15, ty = tid >> 4;
    float acc[4][4] = {};

    for (int k0 = 0; k0 < C_; k0 += 16) {
        #pragma unroll
        for (int j = 0; j < 4; j++) {
            int i = tid + j * 256;
            int m = i >> 4, k = i & 15;
            float v = 0.f;
            if (m0 + m < K_) v = Ab[(long)(m0 + m) * C_ + k0 + k];
            As[k][m] = v;
        }
        #pragma unroll
        for (int j = 0; j < 4; j++) {
            int i = tid + j * 256;
            int n = i >> 4, k = i & 15;
            float v = 0.f;
            if (n0 + n < K_) v = M2[(long)(n0 + n) * C_ + k0 + k];
            Bs[k][n] = v;
        }
        __syncthreads();
        #pragma unroll
        for (int kk = 0; kk < 16; kk++) {
            float a[4], bv[4];
            #pragma unroll
            for (int i = 0; i < 4; i++) a[i] = As[kk][ty + 16 * i];
            #pragma unroll
            for (int j = 0; j < 4; j++) bv[j] = Bs[kk][tx + 16 * j];
            #pragma unroll
            for (int i = 0; i < 4; i++)
                #pragma unroll
                for (int j = 0; j < 4; j++)
                    acc[i][j] += a[i] * bv[j];
        }
        __syncthreads();
    }

    #pragma unroll
    for (int i = 0; i < 4; i++) {
        int m = m0 + ty + 16 * i;
        if (m >= K_) continue;
        #pragma unroll
        for (int j = 0; j < 4; j++) {
            int n = n0 + tx + 16 * j;
            if (n >= KP) continue;
            float v = (n < K_) ? acc[i][j] : 0.f;
            Cb[(long)m * KP + n] = __float2half_rn(v);
        }
    }
}

// ---------------------------------------------------------------------------
// kernel_launch
// ---------------------------------------------------------------------------
extern "C" void kernel_launch(void* const* d_in, const int* in_sizes, int n_in,
                              void* d_out, int out_size)
{
    const float* x      = (const float*)d_in[0];
    const float* cls    = (const float*)d_in[1];
    const float* W_cls  = (const float*)d_in[2];
    const float* W_feat = (const float*)d_in[3];
    const float* gamma  = (const float*)d_in[4];
    const float* beta   = (const float*)d_in[5];
    float* out = (float*)d_out;

    __half *h2, *STT2;
    float *P, *Ppart, *M2, *clsT, *aclsT, *rpart, *rinv, *cinv;
    cudaGetSymbolAddress((void**)&h2,    g_h2);
    cudaGetSymbolAddress((void**)&P,     g_P);
    cudaGetSymbolAddress((void**)&Ppart, g_Ppart);
    cudaGetSymbolAddress((void**)&M2,    g_M2);
    cudaGetSymbolAddress((void**)&clsT,  g_clsT);
    cudaGetSymbolAddress((void**)&aclsT, g_aclsT);
    cudaGetSymbolAddress((void**)&STT2,  g_STT2);
    cudaGetSymbolAddress((void**)&rpart, g_rpart);
    cudaGetSymbolAddress((void**)&rinv,  g_rinv);
    cudaGetSymbolAddress((void**)&cinv,  g_cinv);

    cudaFuncSetAttribute(k_attn,  cudaFuncAttributeMaxDynamicSharedMemorySize, SMEM_GEMM_B);
    cudaFuncSetAttribute(k2_pgemm, cudaFuncAttributeMaxDynamicSharedMemorySize, SMEM_GEMM_B);
    cudaFuncSetAttribute(k_masks, cudaFuncAttributeMaxDynamicSharedMemorySize, SMEM_MASK_B);

    // prep: tf32 cls, zero h2 padding rows, M2 = cls @ W_feat^T
    conv_tf32<<<(K_ * C_ + 255) / 256, 256>>>(cls, clsT, K_ * C_);
    zero_hpad<<<(B_ * (KP - K_) * N_ + 255) / 256, 256>>>(h2);
    gemm_nt<<<dim3(8, 3, 1), 256>>>(cls, C_, W_feat, C_, M2, C_, K_, C_, C_);

    // h2 = fp16(exp(attn)) + row partials + col inverses
    k_attn<<<dim3(N_ / BM, 1, B_), 256, SMEM_GEMM_B>>>(x, clsT, h2, rpart, cinv);
    reduce_rinv<<<(B_ * K_ + 255) / 256, 256>>>(rpart, rinv);

    // P = rowsoftmax @ img_feat  (unnormalized in k2, scaled in reduce)
    k2_pgemm<<<dim3(C_ / BM, NSPLIT, B_), 256, SMEM_GEMM_B>>>(x, h2, Ppart);
    reduce_P<<<(B_ * K_ * C_ + 255) / 256, 256>>>(Ppart, rinv, P);

    // aclsT = tf32(cls + P @ W_cls^T); STT2 = fp16(aclsT @ M2^T) padded
    gemm_acls<<<dim3(8, 3, B_), 256>>>(P, W_cls, cls, aclsT);
    gemm_STT<<<dim3(3, 3, B_), 256>>>(aclsT, M2, STT2);

    // out = LN( acls·x + ST·(h·cinv) )
    k_masks<<<dim3(N_ / BM, 1, B_), 256, SMEM_MASK_B>>>(
        x, aclsT, STT2, h2, cinv, gamma, beta, out);
}

// round 13
// speedup vs baseline: 1.4632x; 1.3390x over previous
#include <cuda_runtime.h>
#include <cuda_fp16.h>
#include <cstdint>

// Problem constants
#define B_  8
#define C_  512
#define N_  16384
#define K_  150
#define KP  160          // K padded
#define NSPLIT 8
#define CHUNK (N_ / NSPLIT)   // 2048

// Tile config
#define BM  128
#define BN  160
#define BK  32
#define BMp 136   // [k][m] pad (fp32 words or halves)
#define BKp 36    // fp32 [n][k] pad (words)
#define BKh 40    // fp16 [.][k] pad (halves)

// k_attn (tf32) stage: As 32*BMp + Bs BN*BKp  (words)
#define STG_A (32 * BMp + BN * BKp)           // 10112
// k2 (fp16) stage: As 128*BKh/2 + Bs 160*BKh/2  (words)
#define STG_2 ((BM * BKh + BN * BKh) / 2)     // 5760
#define AB2   (BM * BKh / 2)                  // 2560 words
// k_masks (fp16) stage: As 32*BMp/2 + Bs 160*BKh/2 (words)
#define STG_M ((32 * BMp + BN * BKh) / 2)     // 5376
#define ABM   (32 * BMp / 2)                  // 2176 words

#define CS_W  (BN * BMp)                      // 21760 words
#define SMEM_ATTN_B  ((CS_W + 128) * 4)       // + ci_s
#define SMEM_K2_B    (CS_W * 4)
#define MU_OFF  CS_W
#define RS_OFF  (CS_W + 128)
#define SMEM_MASK_B  ((CS_W + 256) * 4)

// ---------------------------------------------------------------------------
// Device scratch
// ---------------------------------------------------------------------------
__device__ __half g_x16 [B_ * C_ * N_];     // fp16 x, written by k_attn
__device__ __half g_h16 [B_ * KP * N_];     // raw exp(attn), pad rows zero
__device__ __half g_hc16[B_ * KP * N_];     // exp(attn)*cinv, pad rows zero
__device__ float  g_P   [B_ * K_ * C_];
__device__ float  g_Ppart[NSPLIT * B_ * K_ * C_];
__device__ float  g_M2  [K_ * C_];
__device__ float  g_clsT[K_ * C_];
__device__ float  g_acls[B_ * K_ * C_];
__device__ __half g_acls16[B_ * K_ * C_];
__device__ __half g_STT16 [B_ * K_ * KP];   // cols >=150 zero
__device__ float  g_rpart[B_ * 128 * KP];
__device__ float  g_rinv[B_ * K_];
__device__ float  g_cinv[B_ * N_];

// ---------------------------------------------------------------------------
// helpers
// ---------------------------------------------------------------------------
__device__ __forceinline__ uint32_t f2tf(float f) {
    uint32_t u;
    asm("cvt.rna.tf32.f32 %0, %1;" : "=r"(u) : "f"(f));
    return u;
}
__device__ __forceinline__ void mma8(float* c,
                                     uint32_t a0, uint32_t a1, uint32_t a2, uint32_t a3,
                                     uint32_t b0, uint32_t b1) {
    asm("mma.sync.aligned.m16n8k8.row.col.f32.tf32.tf32.f32 "
        "{%0,%1,%2,%3}, {%4,%5,%6,%7}, {%8,%9}, {%0,%1,%2,%3};"
        : "+f"(c[0]), "+f"(c[1]), "+f"(c[2]), "+f"(c[3])
        : "r"(a0), "r"(a1), "r"(a2), "r"(a3), "r"(b0), "r"(b1));
}
__device__ __forceinline__ void mma16(float* c,
                                      uint32_t a0, uint32_t a1, uint32_t a2, uint32_t a3,
                                      uint32_t b0, uint32_t b1) {
    asm("mma.sync.aligned.m16n8k16.row.col.f32.f16.f16.f32 "
        "{%0,%1,%2,%3}, {%4,%5,%6,%7}, {%8,%9}, {%0,%1,%2,%3};"
        : "+f"(c[0]), "+f"(c[1]), "+f"(c[2]), "+f"(c[3])
        : "r"(a0), "r"(a1), "r"(a2), "r"(a3), "r"(b0), "r"(b1));
}
__device__ __forceinline__ void ldmx4(uint32_t& r0, uint32_t& r1, uint32_t& r2, uint32_t& r3,
                                      uint32_t addr) {
    asm volatile("ldmatrix.sync.aligned.m8n8.x4.shared.b16 {%0,%1,%2,%3}, [%4];"
                 : "=r"(r0), "=r"(r1), "=r"(r2), "=r"(r3) : "r"(addr));
}
__device__ __forceinline__ void ldmx4t(uint32_t& r0, uint32_t& r1, uint32_t& r2, uint32_t& r3,
                                       uint32_t addr) {
    asm volatile("ldmatrix.sync.aligned.m8n8.x4.trans.shared.b16 {%0,%1,%2,%3}, [%4];"
                 : "=r"(r0), "=r"(r1), "=r"(r2), "=r"(r3) : "r"(addr));
}
__device__ __forceinline__ void ldmx2(uint32_t& r0, uint32_t& r1, uint32_t addr) {
    asm volatile("ldmatrix.sync.aligned.m8n8.x2.shared.b16 {%0,%1}, [%2];"
                 : "=r"(r0), "=r"(r1) : "r"(addr));
}
__device__ __forceinline__ void cpa16(const void* smem, const void* gmem) {
    uint32_t s = (uint32_t)__cvta_generic_to_shared(smem);
    asm volatile("cp.async.cg.shared.global [%0], [%1], 16;" :: "r"(s), "l"(gmem));
}
#define CPA_COMMIT asm volatile("cp.async.commit_group;")
#define CPA_WAIT0  asm volatile("cp.async.wait_group 0;")

// ---------------------------------------------------------------------------
// k_attn (tf32 mainloop, R10-proven): h = exp(cls·x); emits x16, h16, hc16,
// row partial sums, cinv. m=pixel(128), n=class(160). 256 thr, warps 4x2.
// ---------------------------------------------------------------------------
__global__ __launch_bounds__(256, 2) void k_attn(
    const float* __restrict__ x, const float* __restrict__ clsT,
    __half* __restrict__ x16, __half* __restrict__ h16, __half* __restrict__ hc16,
    float* __restrict__ rpart, float* __restrict__ cinv)
{
    extern __shared__ uint32_t sm[];
    float* Cs   = (float*)sm;
    float* ci_s = (float*)(sm + CS_W);

    const int tid = threadIdx.x, lane = tid & 31, warp = tid >> 5;
    const int wm = (warp & 3) * 32, wn = (warp >> 2) * 80;
    const int m0 = blockIdx.x * BM;
    const int b  = blockIdx.z;
    const float* Xb   = x   + (long)b * C_ * N_;
    __half*      X16b = x16 + (long)b * C_ * N_;

    auto issue = [&](int kt, int st) {
        uint32_t* As = sm + st * STG_A;
        uint32_t* Bs = As + 32 * BMp;
        const int k0 = kt * BK;
        #pragma unroll
        for (int p = 0; p < 4; p++) {
            int slot = tid + p * 256;
            int r = slot >> 5, c = slot & 31;
            cpa16(As + r * BMp + c * 4, Xb + (long)(k0 + r) * N_ + m0 + c * 4);
        }
        #pragma unroll
        for (int p = 0; p < 5; p++) {
            int slot = tid + p * 256;
            if (slot < K_ * 8) {
                int r = slot >> 3, c = slot & 7;
                cpa16(Bs + r * BKp + c * 4, clsT + (long)r * C_ + k0 + c * 4);
            }
        }
        CPA_COMMIT;
    };

    issue(0, 0);
    float acc[2][10][4] = {};
    const int KT = C_ / BK;                             // 16
    for (int kt = 0; kt < KT; kt++) {
        const int cur = kt & 1;
        CPA_WAIT0;
        __syncthreads();
        if (kt + 1 < KT) issue(kt + 1, cur ^ 1);
        uint32_t* As = sm + cur * STG_A;
        uint32_t* Bs = As + 32 * BMp;
        #pragma unroll
        for (int ks = 0; ks < 4; ks++) {
            uint32_t a[2][4], bb[10][2];
            const int kc = ks * 8 + (lane & 3);
            #pragma unroll
            for (int mi = 0; mi < 2; mi++) {
                int mr = wm + mi * 16 + (lane >> 2);
                a[mi][0] = As[kc * BMp + mr];       a[mi][1] = As[kc * BMp + mr + 8];
                a[mi][2] = As[(kc + 4) * BMp + mr]; a[mi][3] = As[(kc + 4) * BMp + mr + 8];
            }
            #pragma unroll
            for (int ni = 0; ni < 10; ni++) {
                int nc = wn + ni * 8 + (lane >> 2);
                bb[ni][0] = Bs[nc * BKp + kc]; bb[ni][1] = Bs[nc * BKp + kc + 4];
            }
            #pragma unroll
            for (int mi = 0; mi < 2; mi++)
                #pragma unroll
                for (int ni = 0; ni < 10; ni++)
                    mma8(acc[mi][ni], a[mi][0], a[mi][1], a[mi][2], a[mi][3],
                         bb[ni][0], bb[ni][1]);
        }
        // emit x16 for this tile (As holds raw fp32 x; safe: next overwrite of
        // this stage happens after the next __syncthreads)
        {
            const int k0 = kt * BK;
            int r = tid >> 3, seg = tid & 7;
            const float* Ap = (const float*)As + r * BMp + seg * 16;
            __half hv[16];
            #pragma unroll
            for (int j = 0; j < 16; j++) hv[j] = __float2half_rn(Ap[j]);
            *(uint4*)(X16b + (long)(k0 + r) * N_ + m0 + seg * 16)     = *(uint4*)(hv);
            *(uint4*)(X16b + (long)(k0 + r) * N_ + m0 + seg * 16 + 8) = *(uint4*)(hv + 8);
        }
    }
    __syncthreads();

    // stage h = exp(acc) into Cs[class][pixel]
    #pragma unroll
    for (int mi = 0; mi < 2; mi++)
        #pragma unroll
        for (int ni = 0; ni < 10; ni++) {
            int mr = wm + mi * 16 + (lane >> 2);
            int nc = wn + ni * 8 + (lane & 3) * 2;
            Cs[ nc      * BMp + mr    ] = expf(acc[mi][ni][0]);
            Cs[(nc + 1) * BMp + mr    ] = expf(acc[mi][ni][1]);
            Cs[ nc      * BMp + mr + 8] = expf(acc[mi][ni][2]);
            Cs[(nc + 1) * BMp + mr + 8] = expf(acc[mi][ni][3]);
        }
    __syncthreads();

    if (tid < BM) {
        float s = 0.f;
        for (int k = 0; k < K_; k++) s += Cs[k * BMp + tid];
        float ci = 1.f / s;
        ci_s[tid] = ci;
        cinv[(long)b * N_ + m0 + tid] = ci;
    }
    __syncthreads();

    __half* Hb  = h16  + (long)b * KP * N_;
    __half* HCb = hc16 + (long)b * KP * N_;
    #pragma unroll
    for (int i = 0; i < 19; i++) {
        int r = warp + i * 8;
        if (r < K_) {
            int ml = lane * 4;
            float4 v = *(float4*)(Cs + r * BMp + ml);
            __half2 p0 = __floats2half2_rn(v.x, v.y);
            __half2 p1 = __floats2half2_rn(v.z, v.w);
            *(uint2*)(Hb + (long)r * N_ + m0 + ml) =
                make_uint2(*(uint32_t*)&p0, *(uint32_t*)&p1);
            __half2 q0 = __floats2half2_rn(v.x * ci_s[ml], v.y * ci_s[ml + 1]);
            __half2 q1 = __floats2half2_rn(v.z * ci_s[ml + 2], v.w * ci_s[ml + 3]);
            *(uint2*)(HCb + (long)r * N_ + m0 + ml) =
                make_uint2(*(uint32_t*)&q0, *(uint32_t*)&q1);
            float s = v.x + v.y + v.z + v.w;
            #pragma unroll
            for (int o = 16; o > 0; o >>= 1) s += __shfl_xor_sync(0xffffffffu, s, o);
            if (lane == 0) rpart[((long)b * 128 + blockIdx.x) * KP + r] = s;
        }
    }
}

// ---------------------------------------------------------------------------
// k2_pgemm (fp16): Ppart[split][b][k][c] = sum_pix h16[k][pix]*x16[c][pix]
// m=channel(128), n=class(160). warps 2(m)x4(n); acc[4][5][4].
// A = x16 [m][k] (normal ldmatrix), B = h16 [n][k] (normal ldmatrix).
// grid (4, NSPLIT, B_)
// ---------------------------------------------------------------------------
__global__ __launch_bounds__(256, 2) void k2_pgemm(
    const __half* __restrict__ x16, const __half* __restrict__ h16,
    float* __restrict__ Pp)
{
    extern __shared__ uint32_t sm[];
    float* Cs = (float*)sm;

    const int tid = threadIdx.x, lane = tid & 31, warp = tid >> 5;
    const int wm = (warp & 1) * 64, wn = (warp >> 1) * 40;
    const int m0 = blockIdx.x * BM;
    const int split = blockIdx.y, b = blockIdx.z;
    const __half* Xb = x16 + (long)b * C_ * N_;
    const __half* Hb = h16 + (long)b * KP * N_;

    const int kbeg = split * CHUNK;
    auto issue = [&](int kt, int st) {
        __half* As16 = (__half*)(sm + st * STG_2);
        __half* Bs16 = (__half*)(sm + st * STG_2 + AB2);
        const int k0 = kbeg + kt * BK;
        #pragma unroll
        for (int p = 0; p < 2; p++) {                   // 512 chunks: [m][k]
            int slot = tid + p * 256;
            int r = slot >> 2, c = slot & 3;
            cpa16(As16 + r * BKh + c * 8, Xb + (long)(m0 + r) * N_ + k0 + c * 8);
        }
        #pragma unroll
        for (int p = 0; p < 3; p++) {                   // 640 chunks: [n][k]
            int slot = tid + p * 256;
            if (slot < KP * 4) {
                int r = slot >> 2, c = slot & 3;
                cpa16(Bs16 + r * BKh + c * 8, Hb + (long)r * N_ + k0 + c * 8);
            }
        }
        CPA_COMMIT;
    };

    issue(0, 0);
    float acc[4][5][4] = {};
    const int KT = CHUNK / BK;                          // 64
    for (int kt = 0; kt < KT; kt++) {
        const int cur = kt & 1;
        CPA_WAIT0;
        __syncthreads();
        if (kt + 1 < KT) issue(kt + 1, cur ^ 1);
        uint32_t abase = (uint32_t)__cvta_generic_to_shared((__half*)(sm + cur * STG_2));
        uint32_t bbase = (uint32_t)__cvta_generic_to_shared((__half*)(sm + cur * STG_2 + AB2));
        #pragma unroll
        for (int ks = 0; ks < 2; ks++) {                // k16 per step
            uint32_t a[4][4], bb[10];
            #pragma unroll
            for (int mi = 0; mi < 4; mi++) {
                int row = wm + mi * 16 + (lane & 7) + ((lane >> 3) & 1) * 8;
                int col = ks * 16 + ((lane >> 4) & 1) * 8;
                ldmx4(a[mi][0], a[mi][1], a[mi][2], a[mi][3],
                      abase + (row * BKh + col) * 2);
            }
            #pragma unroll
            for (int bj = 0; bj < 2; bj++) {
                int nrow = wn + bj * 16 + (lane & 7) + ((lane >> 4) & 1) * 8;
                int col = ks * 16 + ((lane >> 3) & 1) * 8;
                ldmx4(bb[bj * 4], bb[bj * 4 + 1], bb[bj * 4 + 2], bb[bj * 4 + 3],
                      bbase + (nrow * BKh + col) * 2);
            }
            {
                int nrow = wn + 32 + (lane & 7);
                int col = ks * 16 + ((lane >> 3) & 1) * 8;
                ldmx2(bb[8], bb[9], bbase + (nrow * BKh + col) * 2);
            }
            #pragma unroll
            for (int mi = 0; mi < 4; mi++)
                #pragma unroll
                for (int ni = 0; ni < 5; ni++)
                    mma16(acc[mi][ni], a[mi][0], a[mi][1], a[mi][2], a[mi][3],
                          bb[2 * ni], bb[2 * ni + 1]);
        }
    }
    __syncthreads();

    #pragma unroll
    for (int mi = 0; mi < 4; mi++)
        #pragma unroll
        for (int ni = 0; ni < 5; ni++) {
            int mr = wm + mi * 16 + (lane >> 2);
            int nc = wn + ni * 8 + (lane & 3) * 2;
            Cs[ nc      * BMp + mr    ] = acc[mi][ni][0];
            Cs[(nc + 1) * BMp + mr    ] = acc[mi][ni][1];
            Cs[ nc      * BMp + mr + 8] = acc[mi][ni][2];
            Cs[(nc + 1) * BMp + mr + 8] = acc[mi][ni][3];
        }
    __syncthreads();

    float* Pb = Pp + ((long)split * B_ + b) * K_ * C_;
    #pragma unroll
    for (int i = 0; i < 19; i++) {
        int r = warp + i * 8;
        if (r < K_) {
            float4 v = *(float4*)(Cs + r * BMp + lane * 4);
            *(float4*)(Pb + (long)r * C_ + m0 + lane * 4) = v;
        }
    }
}

// ---------------------------------------------------------------------------
// k_masks (fp16): out = LN_k( acls·x + ST·hc ). 21 uniform tiles:
// 0..15: A=x16 [k][m] (x4.trans), B=acls16 [n][k] (normal)
// 16..20: A=hc16 [k][m],          B=STT16 [n][k]
// m=pixel, n=class. warps 4(m)x2(n); acc[2][10][4]. grid (N_/BM, 1, B_)
// ---------------------------------------------------------------------------
__global__ __launch_bounds__(256, 2) void k_masks(
    const __half* __restrict__ x16, const __half* __restrict__ acls16,
    const __half* __restrict__ STT16, const __half* __restrict__ hc16,
    const float* __restrict__ gamma, const float* __restrict__ beta,
    float* __restrict__ out)
{
    extern __shared__ uint32_t sm[];
    float* Cs   = (float*)sm;
    float* mu_s = (float*)(sm + MU_OFF);
    float* rs_s = (float*)(sm + RS_OFF);

    const int tid = threadIdx.x, lane = tid & 31, warp = tid >> 5;
    const int wm = (warp & 3) * 32, wn = (warp >> 2) * 80;
    const int m0 = blockIdx.x * BM;
    const int b  = blockIdx.z;

    const __half* Xb  = x16    + (long)b * C_ * N_;
    const __half* Ab  = acls16 + (long)b * K_ * C_;
    const __half* Sb  = STT16  + (long)b * K_ * KP;
    const __half* HCb = hc16   + (long)b * KP * N_;

    auto issue = [&](int kt, int st) {
        __half* As16 = (__half*)(sm + st * STG_M);
        __half* Bs16 = (__half*)(sm + st * STG_M + ABM);
        const __half* srcA; const __half* srcB; int k0, ldb;
        if (kt < 16) { srcA = Xb;  srcB = Ab; k0 = kt * BK;        ldb = C_; }
        else         { srcA = HCb; srcB = Sb; k0 = (kt - 16) * BK; ldb = KP; }
        #pragma unroll
        for (int p = 0; p < 2; p++) {                   // 512 chunks: [k][m]
            int slot = tid + p * 256;
            int r = slot >> 4, c = slot & 15;
            cpa16(As16 + r * BMp + c * 8, srcA + (long)(k0 + r) * N_ + m0 + c * 8);
        }
        #pragma unroll
        for (int p = 0; p < 3; p++) {                   // 600 chunks: [n][k]
            int slot = tid + p * 256;
            if (slot < K_ * 4) {
                int r = slot >> 2, c = slot & 3;
                cpa16(Bs16 + r * BKh + c * 8, srcB + (long)r * ldb + k0 + c * 8);
            }
        }
        CPA_COMMIT;
    };

    issue(0, 0);
    float acc[2][10][4] = {};
    const int KT = 16 + 5;
    for (int kt = 0; kt < KT; kt++) {
        const int cur = kt & 1;
        CPA_WAIT0;
        __syncthreads();
        if (kt + 1 < KT) issue(kt + 1, cur ^ 1);
        uint32_t abase = (uint32_t)__cvta_generic_to_shared((__half*)(sm + cur * STG_M));
        uint32_t bbase = (uint32_t)__cvta_generic_to_shared((__half*)(sm + cur * STG_M + ABM));
        #pragma unroll
        for (int ks = 0; ks < 2; ks++) {
            uint32_t a[2][4], bb[20];
            #pragma unroll
            for (int mi = 0; mi < 2; mi++) {            // A from [k][m]: x4.trans
                int krow = ks * 16 + (lane & 7) + ((lane >> 4) & 1) * 8;
                int moff = wm + mi * 16 + ((lane >> 3) & 1) * 8;
                ldmx4t(a[mi][0], a[mi][1], a[mi][2], a[mi][3],
                       abase + (krow * BMp + moff) * 2);
            }
            #pragma unroll
            for (int bj = 0; bj < 5; bj++) {            // B from [n][k]: normal x4
                int nrow = wn + bj * 16 + (lane & 7) + ((lane >> 4) & 1) * 8;
                int col = ks * 16 + ((lane >> 3) & 1) * 8;
                ldmx4(bb[bj * 4], bb[bj * 4 + 1], bb[bj * 4 + 2], bb[bj * 4 + 3],
                      bbase + (nrow * BKh + col) * 2);
            }
            #pragma unroll
            for (int mi = 0; mi < 2; mi++)
                #pragma unroll
                for (int ni = 0; ni < 10; ni++)
                    mma16(acc[mi][ni], a[mi][0], a[mi][1], a[mi][2], a[mi][3],
                          bb[2 * ni], bb[2 * ni + 1]);
        }
    }
    __syncthreads();

    #pragma unroll
    for (int mi = 0; mi < 2; mi++)
        #pragma unroll
        for (int ni = 0; ni < 10; ni++) {
            int mr = wm + mi * 16 + (lane >> 2);
            int nc = wn + ni * 8 + (lane & 3) * 2;
            Cs[ nc      * BMp + mr    ] = acc[mi][ni][0];
            Cs[(nc + 1) * BMp + mr    ] = acc[mi][ni][1];
            Cs[ nc      * BMp + mr + 8] = acc[mi][ni][2];
            Cs[(nc + 1) * BMp + mr + 8] = acc[mi][ni][3];
        }
    __syncthreads();

    if (tid < BM) {
        float s = 0.f, s2 = 0.f;
        for (int k = 0; k < K_; k++) {
            float v = Cs[k * BMp + tid];
            s += v; s2 += v * v;
        }
        float mu  = s * (1.f / K_);
        float var = s2 * (1.f / K_) - mu * mu;
        mu_s[tid] = mu;
        rs_s[tid] = rsqrtf(fmaxf(var, 0.f) + 1e-5f);
    }
    __syncthreads();

    float* Ob = out + (long)b * K_ * N_;
    #pragma unroll
    for (int i = 0; i < 19; i++) {
        int r = warp + i * 8;
        if (r < K_) {
            float g  = __ldg(&gamma[r]);
            float bt = __ldg(&beta[r]);
            int ml = lane * 4;
            float4 v = *(float4*)(Cs + r * BMp + ml);
            v.x = (v.x - mu_s[ml    ]) * rs_s[ml    ] * g + bt;
            v.y = (v.y - mu_s[ml + 1]) * rs_s[ml + 1] * g + bt;
            v.z = (v.z - mu_s[ml + 2]) * rs_s[ml + 2] * g + bt;
            v.w = (v.w - mu_s[ml + 3]) * rs_s[ml + 3] * g + bt;
            *(float4*)(Ob + (long)r * N_ + m0 + ml) = v;
        }
    }
}

// ---------------------------------------------------------------------------
// small kernels
// ---------------------------------------------------------------------------
__global__ void reduce_rinv(const float* __restrict__ rpart, float* __restrict__ rinv)
{
    int idx = blockIdx.x * blockDim.x + threadIdx.x;
    if (idx < B_ * K_) {
        int b = idx / K_, k = idx % K_;
        float s = 0.f;
        for (int blk = 0; blk < 128; blk++)
            s += rpart[((long)b * 128 + blk) * KP + k];
        rinv[idx] = 1.f / s;
    }
}

__global__ void reduce_P(const float* __restrict__ Pp, const float* __restrict__ rinv,
                         float* __restrict__ P)
{
    int i = blockIdx.x * blockDim.x + threadIdx.x;
    if (i < B_ * K_ * C_) {
        int b = i / (K_ * C_);
        int k = (i / C_) % K_;
        float s = 0.f;
        #pragma unroll
        for (int sp = 0; sp < NSPLIT; sp++) s += Pp[(long)sp * B_ * K_ * C_ + i];
        P[i] = s * rinv[b * K_ + k];
    }
}

__global__ void conv_tf32(const float* __restrict__ in, float* __restrict__ out, int n)
{
    int i = blockIdx.x * blockDim.x + threadIdx.x;
    if (i < n) out[i] = __uint_as_float(f2tf(in[i]));
}

__global__ void zero_hpad(__half* __restrict__ h16, __half* __restrict__ hc16)
{
    int i = blockIdx.x * blockDim.x + threadIdx.x;
    int tot = B_ * (KP - K_) * N_;
    if (i < tot) {
        int b = i / ((KP - K_) * N_);
        int rem = i % ((KP - K_) * N_);
        long off = (long)b * KP * N_ + (long)K_ * N_ + rem;
        h16[off] = __float2half(0.f);
        hc16[off] = __float2half(0.f);
    }
}

// plain SIMT NT GEMM (M2 = cls @ W_feat^T)
__global__ void gemm_nt(const float* __restrict__ A, int lda,
                        const float* __restrict__ Bm, int ldb,
                        float* __restrict__ Cm, int ldc,
                        int M, int N, int Kin)
{
    __shared__ float As[16][65];
    __shared__ float Bs[16][65];
    int m0 = blockIdx.y * 64, n0 = blockIdx.x * 64;
    int tid = threadIdx.x;
    int tx = tid & 15, ty = tid >> 4;
    float acc[4][4] = {};

    for (int k0 = 0; k0 < Kin; k0 += 16) {
        #pragma unroll
        for (int j = 0; j < 4; j++) {
            int i = tid + j * 256;
            int m = i >> 4, k = i & 15;
            float v = 0.f;
            if (m0 + m < M && k0 + k < Kin) v = A[(long)(m0 + m) * lda + k0 + k];
            As[k][m] = v;
        }
        #pragma unroll
        for (int j = 0; j < 4; j++) {
            int i = tid + j * 256;
            int n = i >> 4, k = i & 15;
            float v = 0.f;
            if (n0 + n < N && k0 + k < Kin) v = Bm[(long)(n0 + n) * ldb + k0 + k];
            Bs[k][n] = v;
        }
        __syncthreads();
        #pragma unroll
        for (int kk = 0; kk < 16; kk++) {
            float a[4], bv[4];
            #pragma unroll
            for (int i = 0; i < 4; i++) a[i] = As[kk][ty + 16 * i];
            #pragma unroll
            for (int j = 0; j < 4; j++) bv[j] = Bs[kk][tx + 16 * j];
            #pragma unroll
            for (int i = 0; i < 4; i++)
                #pragma unroll
                for (int j = 0; j < 4; j++)
                    acc[i][j] += a[i] * bv[j];
        }
        __syncthreads();
    }

    #pragma unroll
    for (int i = 0; i < 4; i++) {
        int m = m0 + ty + 16 * i;
        if (m >= M) continue;
        #pragma unroll
        for (int j = 0; j < 4; j++) {
            int n = n0 + tx + 16 * j;
            if (n >= N) continue;
            Cm[(long)m * ldc + n] = acc[i][j];
        }
    }
}

// gemm_acls: acls[b] = cls + P[b] @ W_cls^T (fp32 + fp16 copies). grid (8,3,B_)
__global__ void gemm_acls(const float* __restrict__ P, const float* __restrict__ Wc,
                          const float* __restrict__ cls,
                          float* __restrict__ acls, __half* __restrict__ acls16)
{
    __shared__ float As[16][65];
    __shared__ float Bs[16][65];
    const float* Abp = P + (long)blockIdx.z * K_ * C_;
    float*  Cb  = acls   + (long)blockIdx.z * K_ * C_;
    __half* Cb16 = acls16 + (long)blockIdx.z * K_ * C_;
    int m0 = blockIdx.y * 64, n0 = blockIdx.x * 64;
    int tid = threadIdx.x;
    int tx = tid & 15, ty = tid >> 4;
    float acc[4][4] = {};

    for (int k0 = 0; k0 < C_; k0 += 16) {
        #pragma unroll
        for (int j = 0; j < 4; j++) {
            int i = tid + j * 256;
            int m = i >> 4, k = i & 15;
            float v = 0.f;
            if (m0 + m < K_) v = Abp[(long)(m0 + m) * C_ + k0 + k];
            As[k][m] = v;
        }
        #pragma unroll
        for (int j = 0; j < 4; j++) {
            int i = tid + j * 256;
            int n = i >> 4, k = i & 15;
            Bs[k][n] = Wc[(long)(n0 + n) * C_ + k0 + k];
        }
        __syncthreads();
        #pragma unroll
        for (int kk = 0; kk < 16; kk++) {
            float a[4], bv[4];
            #pragma unroll
            for (int i = 0; i < 4; i++) a[i] = As[kk][ty + 16 * i];
            #pragma unroll
            for (int j = 0; j < 4; j++) bv[j] = Bs[kk][tx + 16 * j];
            #pragma unroll
            for (int i = 0; i < 4; i++)
                #pragma unroll
                for (int j = 0; j < 4; j++)
                    acc[i][j] += a[i] * bv[j];
        }
        __syncthreads();
    }

    #pragma unroll
    for (int i = 0; i < 4; i++) {
        int m = m0 + ty + 16 * i;
        if (m >= K_) continue;
        #pragma unroll
        for (int j = 0; j < 4; j++) {
            int n = n0 + tx + 16 * j;
            float v = acc[i][j] + cls[(long)m * C_ + n];
            Cb[(long)m * C_ + n] = v;
            Cb16[(long)m * C_ + n] = __float2half_rn(v);
        }
    }
}

// gemm_STT: STT16[b][k'][k] = fp16( sum_d acls[b][k'][d]*M2[k][d] ), cols
// padded to KP with zeros. grid (3,3,B_)
__global__ void gemm_STT(const float* __restrict__ acls, const float* __restrict__ M2,
                         __half* __restrict__ STT16)
{
    __shared__ float As[16][65];
    __shared__ float Bs[16][65];
    const float* Abp = acls + (long)blockIdx.z * K_ * C_;
    __half*      Cb  = STT16 + (long)blockIdx.z * K_ * KP;
    int m0 = blockIdx.y * 64, n0 = blockIdx.x * 64;
    int tid = threadIdx.x;
    int tx = tid & 15, ty = tid >> 4;
    float acc[4][4] = {};

    for (int k0 = 0; k0 < C_; k0 += 16) {
        #pragma unroll
        for (int j = 0; j < 4; j++) {
            int i = tid + j * 256;
            int m = i >> 4, k = i & 15;
            float v = 0.f;
            if (m0 + m < K_) v = Abp[(long)(m0 + m) * C_ + k0 + k];
            As[k][m] = v;
        }
        #pragma unroll
        for (int j = 0; j < 4; j++) {
            int i = tid + j * 256;
            int n = i >> 4, k = i & 15;
            float v = 0.f;
            if (n0 + n < K_) v = M2[(long)(n0 + n) * C_ + k0 + k];
            Bs[k][n] = v;
        }
        __syncthreads();
        #pragma unroll
        for (int kk = 0; kk < 16; kk++) {
            float a[4], bv[4];
            #pragma unroll
            for (int i = 0; i < 4; i++) a[i] = As[kk][ty + 16 * i];
            #pragma unroll
            for (int j = 0; j < 4; j++) bv[j] = Bs[kk][tx + 16 * j];
            #pragma unroll
            for (int i = 0; i < 4; i++)
                #pragma unroll
                for (int j = 0; j < 4; j++)
                    acc[i][j] += a[i] * bv[j];
        }
        __syncthreads();
    }

    #pragma unroll
    for (int i = 0; i < 4; i++) {
        int m = m0 + ty + 16 * i;
        if (m >= K_) continue;
        #pragma unroll
        for (int j = 0; j < 4; j++) {
            int n = n0 + tx + 16 * j;
            if (n >= KP) continue;
            float v = (n < K_) ? acc[i][j] : 0.f;
            Cb[(long)m * KP + n] = __float2half_rn(v);
        }
    }
}

// ---------------------------------------------------------------------------
// kernel_launch
// ---------------------------------------------------------------------------
extern "C" void kernel_launch(void* const* d_in, const int* in_sizes, int n_in,
                              void* d_out, int out_size)
{
    const float* x      = (const float*)d_in[0];
    const float* cls    = (const float*)d_in[1];
    const float* W_cls  = (const float*)d_in[2];
    const float* W_feat = (const float*)d_in[3];
    const float* gamma  = (const float*)d_in[4];
    const float* beta   = (const float*)d_in[5];
    float* out = (float*)d_out;

    __half *x16, *h16, *hc16, *acls16, *STT16;
    float *P, *Ppart, *M2, *clsT, *acls, *rpart, *rinv, *cinv;
    cudaGetSymbolAddress((void**)&x16,   g_x16);
    cudaGetSymbolAddress((void**)&h16,   g_h16);
    cudaGetSymbolAddress((void**)&hc16,  g_hc16);
    cudaGetSymbolAddress((void**)&P,     g_P);
    cudaGetSymbolAddress((void**)&Ppart, g_Ppart);
    cudaGetSymbolAddress((void**)&M2,    g_M2);
    cudaGetSymbolAddress((void**)&clsT,  g_clsT);
    cudaGetSymbolAddress((void**)&acls,  g_acls);
    cudaGetSymbolAddress((void**)&acls16, g_acls16);
    cudaGetSymbolAddress((void**)&STT16, g_STT16);
    cudaGetSymbolAddress((void**)&rpart, g_rpart);
    cudaGetSymbolAddress((void**)&rinv,  g_rinv);
    cudaGetSymbolAddress((void**)&cinv,  g_cinv);

    cudaFuncSetAttribute(k_attn,  cudaFuncAttributeMaxDynamicSharedMemorySize, SMEM_ATTN_B);
    cudaFuncSetAttribute(k2_pgemm, cudaFuncAttributeMaxDynamicSharedMemorySize, SMEM_K2_B);
    cudaFuncSetAttribute(k_masks, cudaFuncAttributeMaxDynamicSharedMemorySize, SMEM_MASK_B);

    // prep
    conv_tf32<<<(K_ * C_ + 255) / 256, 256>>>(cls, clsT, K_ * C_);
    zero_hpad<<<(B_ * (KP - K_) * N_ + 255) / 256, 256>>>(h16, hc16);
    gemm_nt<<<dim3(8, 3, 1), 256>>>(cls, C_, W_feat, C_, M2, C_, K_, C_, C_);

    // h16/hc16 = exp(attn) (+cinv scaled); x16 emitted; row partials; cinv
    k_attn<<<dim3(N_ / BM, 1, B_), 256, SMEM_ATTN_B>>>(
        x, clsT, x16, h16, hc16, rpart, cinv);
    reduce_rinv<<<(B_ * K_ + 255) / 256, 256>>>(rpart, rinv);

    // P = rowsoftmax @ img_feat (fp16 mma, unnormalized; scaled in reduce)
    k2_pgemm<<<dim3(C_ / BM, NSPLIT, B_), 256, SMEM_K2_B>>>(x16, h16, Ppart);
    reduce_P<<<(B_ * K_ * C_ + 255) / 256, 256>>>(Ppart, rinv, P);

    // acls = cls + P @ W_cls^T (fp32 + fp16); STT16 = fp16(acls @ M2^T) padded
    gemm_acls<<<dim3(8, 3, B_), 256>>>(P, W_cls, cls, acls, acls16);
    gemm_STT<<<dim3(3, 3, B_), 256>>>(acls, M2, STT16);

    // out = LN( acls·x + ST·hc )   (fp16 mma, uniform 21-tile pipeline)
    k_masks<<<dim3(N_ / BM, 1, B_), 256, SMEM_MASK_B>>>(
        x16, acls16, STT16, hc16, gamma, beta, out);
}

// round 15
// speedup vs baseline: 1.5609x; 1.0668x over previous
#include <cuda_runtime.h>
#include <cuda_fp16.h>
#include <cstdint>

// Problem constants
#define B_  8
#define C_  512
#define N_  16384
#define K_  150
#define KP  160          // K padded
#define NSPLIT 8
#define CHUNK (N_ / NSPLIT)   // 2048

// Tile config
#define BM  128
#define BN  160
#define BK  32
#define BMp 136   // [k][m] pad (halves or fp32 words)
#define BKh 40    // fp16 [.][k] pad (halves)

// k_attn stage (words): As32 fp32 [32][BMp] + As16 fp16 [32][BMp] + Bs16 [160][BKh]
#define AS16_OFF  (32 * BMp)                  // 4352 words
#define BS16A_OFF (AS16_OFF + 32 * BMp / 2)   // 4352 + 2176 = 6528 words
#define STG_A2    (BS16A_OFF + BN * BKh / 2)  // 6528 + 3200 = 9728 words

// k2 (fp16) stage: As 128*BKh/2 + Bs 160*BKh/2  (words)
#define STG_2 ((BM * BKh + BN * BKh) / 2)     // 5760
#define AB2   (BM * BKh / 2)                  // 2560 words
// k_masks (fp16) stage: As 32*BMp/2 + Bs 160*BKh/2 (words)
#define STG_M ((32 * BMp + BN * BKh) / 2)     // 5376
#define ABM   (32 * BMp / 2)                  // 2176 words

#define CS_W  (BN * BMp)                      // 21760 words
#define SMEM_ATTN_B  ((CS_W + 128) * 4)       // 87552 (also covers 2*STG_A2=19456 w)
#define SMEM_K2_B    (CS_W * 4)
#define MU_OFF  CS_W
#define RS_OFF  (CS_W + 128)
#define SMEM_MASK_B  ((CS_W + 256) * 4)

// ---------------------------------------------------------------------------
// Device scratch
// ---------------------------------------------------------------------------
__device__ __half g_x16 [B_ * C_ * N_];     // fp16 x, written by k_attn
__device__ __half g_h16 [B_ * KP * N_];     // raw exp(attn), pad rows zero
__device__ __half g_hc16[B_ * KP * N_];     // exp(attn)*cinv, pad rows zero
__device__ __half g_cls16[K_ * C_];
__device__ float  g_P   [B_ * K_ * C_];
__device__ float  g_Ppart[NSPLIT * B_ * K_ * C_];
__device__ float  g_M2  [K_ * C_];
__device__ float  g_acls[B_ * K_ * C_];
__device__ __half g_acls16[B_ * K_ * C_];
__device__ __half g_STT16 [B_ * K_ * KP];   // cols >=150 zero
__device__ float  g_rpart[B_ * 128 * KP];
__device__ float  g_rinv[B_ * K_];
__device__ float  g_cinv[B_ * N_];

// ---------------------------------------------------------------------------
// helpers
// ---------------------------------------------------------------------------
__device__ __forceinline__ void mma16(float* c,
                                      uint32_t a0, uint32_t a1, uint32_t a2, uint32_t a3,
                                      uint32_t b0, uint32_t b1) {
    asm("mma.sync.aligned.m16n8k16.row.col.f32.f16.f16.f32 "
        "{%0,%1,%2,%3}, {%4,%5,%6,%7}, {%8,%9}, {%0,%1,%2,%3};"
        : "+f"(c[0]), "+f"(c[1]), "+f"(c[2]), "+f"(c[3])
        : "r"(a0), "r"(a1), "r"(a2), "r"(a3), "r"(b0), "r"(b1));
}
__device__ __forceinline__ void ldmx4(uint32_t& r0, uint32_t& r1, uint32_t& r2, uint32_t& r3,
                                      uint32_t addr) {
    asm volatile("ldmatrix.sync.aligned.m8n8.x4.shared.b16 {%0,%1,%2,%3}, [%4];"
                 : "=r"(r0), "=r"(r1), "=r"(r2), "=r"(r3) : "r"(addr));
}
__device__ __forceinline__ void ldmx4t(uint32_t& r0, uint32_t& r1, uint32_t& r2, uint32_t& r3,
                                       uint32_t addr) {
    asm volatile("ldmatrix.sync.aligned.m8n8.x4.trans.shared.b16 {%0,%1,%2,%3}, [%4];"
                 : "=r"(r0), "=r"(r1), "=r"(r2), "=r"(r3) : "r"(addr));
}
__device__ __forceinline__ void ldmx2(uint32_t& r0, uint32_t& r1, uint32_t addr) {
    asm volatile("ldmatrix.sync.aligned.m8n8.x2.shared.b16 {%0,%1}, [%2];"
                 : "=r"(r0), "=r"(r1) : "r"(addr));
}
__device__ __forceinline__ void cpa16(const void* smem, const void* gmem) {
    uint32_t s = (uint32_t)__cvta_generic_to_shared(smem);
    asm volatile("cp.async.cg.shared.global [%0], [%1], 16;" :: "r"(s), "l"(gmem));
}
#define CPA_COMMIT asm volatile("cp.async.commit_group;")
#define CPA_WAIT0  asm volatile("cp.async.wait_group 0;")

// ---------------------------------------------------------------------------
// k_attn (fp16 mma): h = exp(cls·x); emits x16 (fused with in-tile fp32->fp16
// conversion), h16, hc16, row partial sums, cinv.
// m=pixel(128), n=class(160). 256 thr, warps 4(m) x 2(n); acc[2][10][4].
// grid (N_/BM, 1, B_)
// ---------------------------------------------------------------------------
__global__ __launch_bounds__(256, 2) void k_attn(
    const float* __restrict__ x, const __half* __restrict__ cls16,
    __half* __restrict__ x16, __half* __restrict__ h16, __half* __restrict__ hc16,
    float* __restrict__ rpart, float* __restrict__ cinv)
{
    extern __shared__ uint32_t sm[];
    float* Cs   = (float*)sm;
    float* ci_s = (float*)(sm + CS_W);

    const int tid = threadIdx.x, lane = tid & 31, warp = tid >> 5;
    const int wm = (warp & 3) * 32, wn = (warp >> 2) * 80;
    const int m0 = blockIdx.x * BM;
    const int b  = blockIdx.z;
    const float* Xb   = x   + (long)b * C_ * N_;
    __half*      X16b = x16 + (long)b * C_ * N_;

    auto issue = [&](int kt, int st) {
        uint32_t* As32 = sm + st * STG_A2;
        __half*   Bs16 = (__half*)(sm + st * STG_A2 + BS16A_OFF);
        const int k0 = kt * BK;
        #pragma unroll
        for (int p = 0; p < 4; p++) {                   // As32[k][m] <- x fp32
            int slot = tid + p * 256;
            int r = slot >> 5, c = slot & 31;
            cpa16(As32 + r * BMp + c * 4, Xb + (long)(k0 + r) * N_ + m0 + c * 4);
        }
        #pragma unroll
        for (int p = 0; p < 3; p++) {                   // Bs16[n][k] <- cls16
            int slot = tid + p * 256;
            if (slot < K_ * 4) {
                int r = slot >> 2, c = slot & 3;
                cpa16(Bs16 + r * BKh + c * 8, cls16 + (long)r * C_ + k0 + c * 8);
            }
        }
        CPA_COMMIT;
    };

    issue(0, 0);
    float acc[2][10][4] = {};
    const int KT = C_ / BK;                             // 16
    for (int kt = 0; kt < KT; kt++) {
        const int cur = kt & 1;
        CPA_WAIT0;
        __syncthreads();
        if (kt + 1 < KT) issue(kt + 1, cur ^ 1);

        // convert staged fp32 x -> fp16 smem tile, fused with x16 global emit
        {
            const int k0 = kt * BK;
            int r = tid >> 3, seg = tid & 7;
            const float* src = (const float*)(sm + cur * STG_A2) + r * BMp + seg * 16;
            __half hv[16];
            #pragma unroll
            for (int j = 0; j < 16; j++) hv[j] = __float2half_rn(src[j]);
            __half* d16 = (__half*)(sm + cur * STG_A2 + AS16_OFF) + r * BMp + seg * 16;
            *(uint4*)d16       = *(uint4*)hv;
            *(uint4*)(d16 + 8) = *(uint4*)(hv + 8);
            __half* g = X16b + (long)(k0 + r) * N_ + m0 + seg * 16;
            *(uint4*)g       = *(uint4*)hv;
            *(uint4*)(g + 8) = *(uint4*)(hv + 8);
        }
        __syncthreads();

        uint32_t abase = (uint32_t)__cvta_generic_to_shared(
            (__half*)(sm + cur * STG_A2 + AS16_OFF));
        uint32_t bbase = (uint32_t)__cvta_generic_to_shared(
            (__half*)(sm + cur * STG_A2 + BS16A_OFF));
        #pragma unroll
        for (int ks = 0; ks < 2; ks++) {
            uint32_t a[2][4], bb[20];
            #pragma unroll
            for (int mi = 0; mi < 2; mi++) {            // A from [k][m]: x4.trans
                int krow = ks * 16 + (lane & 7) + ((lane >> 4) & 1) * 8;
                int moff = wm + mi * 16 + ((lane >> 3) & 1) * 8;
                ldmx4t(a[mi][0], a[mi][1], a[mi][2], a[mi][3],
                       abase + (krow * BMp + moff) * 2);
            }
            #pragma unroll
            for (int bj = 0; bj < 5; bj++) {            // B from [n][k]: normal x4
                int nrow = wn + bj * 16 + (lane & 7) + ((lane >> 4) & 1) * 8;
                int col = ks * 16 + ((lane >> 3) & 1) * 8;
                ldmx4(bb[bj * 4], bb[bj * 4 + 1], bb[bj * 4 + 2], bb[bj * 4 + 3],
                      bbase + (nrow * BKh + col) * 2);
            }
            #pragma unroll
            for (int mi = 0; mi < 2; mi++)
                #pragma unroll
                for (int ni = 0; ni < 10; ni++)
                    mma16(acc[mi][ni], a[mi][0], a[mi][1], a[mi][2], a[mi][3],
                          bb[2 * ni], bb[2 * ni + 1]);
        }
    }
    __syncthreads();

    // stage h = exp(acc) into Cs[class][pixel]
    #pragma unroll
    for (int mi = 0; mi < 2; mi++)
        #pragma unroll
        for (int ni = 0; ni < 10; ni++) {
            int mr = wm + mi * 16 + (lane >> 2);
            int nc = wn + ni * 8 + (lane & 3) * 2;
            Cs[ nc      * BMp + mr    ] = expf(acc[mi][ni][0]);
            Cs[(nc + 1) * BMp + mr    ] = expf(acc[mi][ni][1]);
            Cs[ nc      * BMp + mr + 8] = expf(acc[mi][ni][2]);
            Cs[(nc + 1) * BMp + mr + 8] = expf(acc[mi][ni][3]);
        }
    __syncthreads();

    if (tid < BM) {
        float s = 0.f;
        for (int k = 0; k < K_; k++) s += Cs[k * BMp + tid];
        float ci = 1.f / s;
        ci_s[tid] = ci;
        cinv[(long)b * N_ + m0 + tid] = ci;
    }
    __syncthreads();

    __half* Hb  = h16  + (long)b * KP * N_;
    __half* HCb = hc16 + (long)b * KP * N_;
    #pragma unroll
    for (int i = 0; i < 19; i++) {
        int r = warp + i * 8;
        if (r < K_) {
            int ml = lane * 4;
            float4 v = *(float4*)(Cs + r * BMp + ml);
            __half2 p0 = __floats2half2_rn(v.x, v.y);
            __half2 p1 = __floats2half2_rn(v.z, v.w);
            *(uint2*)(Hb + (long)r * N_ + m0 + ml) =
                make_uint2(*(uint32_t*)&p0, *(uint32_t*)&p1);
            __half2 q0 = __floats2half2_rn(v.x * ci_s[ml], v.y * ci_s[ml + 1]);
            __half2 q1 = __floats2half2_rn(v.z * ci_s[ml + 2], v.w * ci_s[ml + 3]);
            *(uint2*)(HCb + (long)r * N_ + m0 + ml) =
                make_uint2(*(uint32_t*)&q0, *(uint32_t*)&q1);
            float s = v.x + v.y + v.z + v.w;
            #pragma unroll
            for (int o = 16; o > 0; o >>= 1) s += __shfl_xor_sync(0xffffffffu, s, o);
            if (lane == 0) rpart[((long)b * 128 + blockIdx.x) * KP + r] = s;
        }
    }
}

// ---------------------------------------------------------------------------
// k2_pgemm (fp16): Ppart[split][b][k][c] = sum_pix h16[k][pix]*x16[c][pix]
// m=channel(128), n=class(160). warps 2(m)x4(n); acc[4][5][4].
// A = x16 [m][k] (normal ldmatrix), B = h16 [n][k] (normal ldmatrix).
// grid (4, NSPLIT, B_)
// ---------------------------------------------------------------------------
__global__ __launch_bounds__(256, 2) void k2_pgemm(
    const __half* __restrict__ x16, const __half* __restrict__ h16,
    float* __restrict__ Pp)
{
    extern __shared__ uint32_t sm[];
    float* Cs = (float*)sm;

    const int tid = threadIdx.x, lane = tid & 31, warp = tid >> 5;
    const int wm = (warp & 1) * 64, wn = (warp >> 1) * 40;
    const int m0 = blockIdx.x * BM;
    const int split = blockIdx.y, b = blockIdx.z;
    const __half* Xb = x16 + (long)b * C_ * N_;
    const __half* Hb = h16 + (long)b * KP * N_;

    const int kbeg = split * CHUNK;
    auto issue = [&](int kt, int st) {
        __half* As16 = (__half*)(sm + st * STG_2);
        __half* Bs16 = (__half*)(sm + st * STG_2 + AB2);
        const int k0 = kbeg + kt * BK;
        #pragma unroll
        for (int p = 0; p < 2; p++) {                   // [m][k]
            int slot = tid + p * 256;
            int r = slot >> 2, c = slot & 3;
            cpa16(As16 + r * BKh + c * 8, Xb + (long)(m0 + r) * N_ + k0 + c * 8);
        }
        #pragma unroll
        for (int p = 0; p < 3; p++) {                   // [n][k]
            int slot = tid + p * 256;
            if (slot < KP * 4) {
                int r = slot >> 2, c = slot & 3;
                cpa16(Bs16 + r * BKh + c * 8, Hb + (long)r * N_ + k0 + c * 8);
            }
        }
        CPA_COMMIT;
    };

    issue(0, 0);
    float acc[4][5][4] = {};
    const int KT = CHUNK / BK;                          // 64
    for (int kt = 0; kt < KT; kt++) {
        const int cur = kt & 1;
        CPA_WAIT0;
        __syncthreads();
        if (kt + 1 < KT) issue(kt + 1, cur ^ 1);
        uint32_t abase = (uint32_t)__cvta_generic_to_shared((__half*)(sm + cur * STG_2));
        uint32_t bbase = (uint32_t)__cvta_generic_to_shared((__half*)(sm + cur * STG_2 + AB2));
        #pragma unroll
        for (int ks = 0; ks < 2; ks++) {                // k16 per step
            uint32_t a[4][4], bb[10];
            #pragma unroll
            for (int mi = 0; mi < 4; mi++) {
                int row = wm + mi * 16 + (lane & 7) + ((lane >> 3) & 1) * 8;
                int col = ks * 16 + ((lane >> 4) & 1) * 8;
                ldmx4(a[mi][0], a[mi][1], a[mi][2], a[mi][3],
                      abase + (row * BKh + col) * 2);
            }
            #pragma unroll
            for (int bj = 0; bj < 2; bj++) {
                int nrow = wn + bj * 16 + (lane & 7) + ((lane >> 4) & 1) * 8;
                int col = ks * 16 + ((lane >> 3) & 1) * 8;
                ldmx4(bb[bj * 4], bb[bj * 4 + 1], bb[bj * 4 + 2], bb[bj * 4 + 3],
                      bbase + (nrow * BKh + col) * 2);
            }
            {
                int nrow = wn + 32 + (lane & 7);
                int col = ks * 16 + ((lane >> 3) & 1) * 8;
                ldmx2(bb[8], bb[9], bbase + (nrow * BKh + col) * 2);
            }
            #pragma unroll
            for (int mi = 0; mi < 4; mi++)
                #pragma unroll
                for (int ni = 0; ni < 5; ni++)
                    mma16(acc[mi][ni], a[mi][0], a[mi][1], a[mi][2], a[mi][3],
                          bb[2 * ni], bb[2 * ni + 1]);
        }
    }
    __syncthreads();

    #pragma unroll
    for (int mi = 0; mi < 4; mi++)
        #pragma unroll
        for (int ni = 0; ni < 5; ni++) {
            int mr = wm + mi * 16 + (lane >> 2);
            int nc = wn + ni * 8 + (lane & 3) * 2;
            Cs[ nc      * BMp + mr    ] = acc[mi][ni][0];
            Cs[(nc + 1) * BMp + mr    ] = acc[mi][ni][1];
            Cs[ nc      * BMp + mr + 8] = acc[mi][ni][2];
            Cs[(nc + 1) * BMp + mr + 8] = acc[mi][ni][3];
        }
    __syncthreads();

    float* Pb = Pp + ((long)split * B_ + b) * K_ * C_;
    #pragma unroll
    for (int i = 0; i < 19; i++) {
        int r = warp + i * 8;
        if (r < K_) {
            float4 v = *(float4*)(Cs + r * BMp + lane * 4);
            *(float4*)(Pb + (long)r * C_ + m0 + lane * 4) = v;
        }
    }
}

// ---------------------------------------------------------------------------
// k_masks (fp16): out = LN_k( acls·x + ST·hc ). 21 uniform tiles:
// 0..15: A=x16 [k][m] (x4.trans), B=acls16 [n][k]; 16..20: A=hc16, B=STT16.
// m=pixel, n=class. warps 4(m)x2(n); acc[2][10][4]. grid (N_/BM, 1, B_)
// ---------------------------------------------------------------------------
__global__ __launch_bounds__(256, 2) void k_masks(
    const __half* __restrict__ x16, const __half* __restrict__ acls16,
    const __half* __restrict__ STT16, const __half* __restrict__ hc16,
    const float* __restrict__ gamma, const float* __restrict__ beta,
    float* __restrict__ out)
{
    extern __shared__ uint32_t sm[];
    float* Cs   = (float*)sm;
    float* mu_s = (float*)(sm + MU_OFF);
    float* rs_s = (float*)(sm + RS_OFF);

    const int tid = threadIdx.x, lane = tid & 31, warp = tid >> 5;
    const int wm = (warp & 3) * 32, wn = (warp >> 2) * 80;
    const int m0 = blockIdx.x * BM;
    const int b  = blockIdx.z;

    const __half* Xb  = x16    + (long)b * C_ * N_;
    const __half* Ab  = acls16 + (long)b * K_ * C_;
    const __half* Sb  = STT16  + (long)b * K_ * KP;
    const __half* HCb = hc16   + (long)b * KP * N_;

    auto issue = [&](int kt, int st) {
        __half* As16 = (__half*)(sm + st * STG_M);
        __half* Bs16 = (__half*)(sm + st * STG_M + ABM);
        const __half* srcA; const __half* srcB; int k0, ldb;
        if (kt < 16) { srcA = Xb;  srcB = Ab; k0 = kt * BK;        ldb = C_; }
        else         { srcA = HCb; srcB = Sb; k0 = (kt - 16) * BK; ldb = KP; }
        #pragma unroll
        for (int p = 0; p < 2; p++) {                   // [k][m]
            int slot = tid + p * 256;
            int r = slot >> 4, c = slot & 15;
            cpa16(As16 + r * BMp + c * 8, srcA + (long)(k0 + r) * N_ + m0 + c * 8);
        }
        #pragma unroll
        for (int p = 0; p < 3; p++) {                   // [n][k]
            int slot = tid + p * 256;
            if (slot < K_ * 4) {
                int r = slot >> 2, c = slot & 3;
                cpa16(Bs16 + r * BKh + c * 8, srcB + (long)r * ldb + k0 + c * 8);
            }
        }
        CPA_COMMIT;
    };

    issue(0, 0);
    float acc[2][10][4] = {};
    const int KT = 16 + 5;
    for (int kt = 0; kt < KT; kt++) {
        const int cur = kt & 1;
        CPA_WAIT0;
        __syncthreads();
        if (kt + 1 < KT) issue(kt + 1, cur ^ 1);
        uint32_t abase = (uint32_t)__cvta_generic_to_shared((__half*)(sm + cur * STG_M));
        uint32_t bbase = (uint32_t)__cvta_generic_to_shared((__half*)(sm + cur * STG_M + ABM));
        #pragma unroll
        for (int ks = 0; ks < 2; ks++) {
            uint32_t a[2][4], bb[20];
            #pragma unroll
            for (int mi = 0; mi < 2; mi++) {
                int krow = ks * 16 + (lane & 7) + ((lane >> 4) & 1) * 8;
                int moff = wm + mi * 16 + ((lane >> 3) & 1) * 8;
                ldmx4t(a[mi][0], a[mi][1], a[mi][2], a[mi][3],
                       abase + (krow * BMp + moff) * 2);
            }
            #pragma unroll
            for (int bj = 0; bj < 5; bj++) {
                int nrow = wn + bj * 16 + (lane & 7) + ((lane >> 4) & 1) * 8;
                int col = ks * 16 + ((lane >> 3) & 1) * 8;
                ldmx4(bb[bj * 4], bb[bj * 4 + 1], bb[bj * 4 + 2], bb[bj * 4 + 3],
                      bbase + (nrow * BKh + col) * 2);
            }
            #pragma unroll
            for (int mi = 0; mi < 2; mi++)
                #pragma unroll
                for (int ni = 0; ni < 10; ni++)
                    mma16(acc[mi][ni], a[mi][0], a[mi][1], a[mi][2], a[mi][3],
                          bb[2 * ni], bb[2 * ni + 1]);
        }
    }
    __syncthreads();

    #pragma unroll
    for (int mi = 0; mi < 2; mi++)
        #pragma unroll
        for (int ni = 0; ni < 10; ni++) {
            int mr = wm + mi * 16 + (lane >> 2);
            int nc = wn + ni * 8 + (lane & 3) * 2;
            Cs[ nc      * BMp + mr    ] = acc[mi][ni][0];
            Cs[(nc + 1) * BMp + mr    ] = acc[mi][ni][1];
            Cs[ nc      * BMp + mr + 8] = acc[mi][ni][2];
            Cs[(nc + 1) * BMp + mr + 8] = acc[mi][ni][3];
        }
    __syncthreads();

    if (tid < BM) {
        float s = 0.f, s2 = 0.f;
        for (int k = 0; k < K_; k++) {
            float v = Cs[k * BMp + tid];
            s += v; s2 += v * v;
        }
        float mu  = s * (1.f / K_);
        float var = s2 * (1.f / K_) - mu * mu;
        mu_s[tid] = mu;
        rs_s[tid] = rsqrtf(fmaxf(var, 0.f) + 1e-5f);
    }
    __syncthreads();

    float* Ob = out + (long)b * K_ * N_;
    #pragma unroll
    for (int i = 0; i < 19; i++) {
        int r = warp + i * 8;
        if (r < K_) {
            float g  = __ldg(&gamma[r]);
            float bt = __ldg(&beta[r]);
            int ml = lane * 4;
            float4 v = *(float4*)(Cs + r * BMp + ml);
            v.x = (v.x - mu_s[ml    ]) * rs_s[ml    ] * g + bt;
            v.y = (v.y - mu_s[ml + 1]) * rs_s[ml + 1] * g + bt;
            v.z = (v.z - mu_s[ml + 2]) * rs_s[ml + 2] * g + bt;
            v.w = (v.w - mu_s[ml + 3]) * rs_s[ml + 3] * g + bt;
            *(float4*)(Ob + (long)r * N_ + m0 + ml) = v;
        }
    }
}

// ---------------------------------------------------------------------------
// small kernels
// ---------------------------------------------------------------------------
__global__ void reduce_rinv(const float* __restrict__ rpart, float* __restrict__ rinv)
{
    int idx = blockIdx.x * blockDim.x + threadIdx.x;
    if (idx < B_ * K_) {
        int b = idx / K_, k = idx % K_;
        float s = 0.f;
        for (int blk = 0; blk < 128; blk++)
            s += rpart[((long)b * 128 + blk) * KP + k];
        rinv[idx] = 1.f / s;
    }
}

__global__ void reduce_P(const float* __restrict__ Pp, const float* __restrict__ rinv,
                         float* __restrict__ P)
{
    int i = blockIdx.x * blockDim.x + threadIdx.x;
    if (i < B_ * K_ * C_) {
        int b = i / (K_ * C_);
        int k = (i / C_) % K_;
        float s = 0.f;
        #pragma unroll
        for (int sp = 0; sp < NSPLIT; sp++) s += Pp[(long)sp * B_ * K_ * C_ + i];
        P[i] = s * rinv[b * K_ + k];
    }
}

__global__ void conv_cls16(const float* __restrict__ cls, __half* __restrict__ cls16)
{
    int i = blockIdx.x * blockDim.x + threadIdx.x;
    if (i < K_ * C_) cls16[i] = __float2half_rn(cls[i]);
}

__global__ void zero_hpad(__half* __restrict__ h16, __half* __restrict__ hc16)
{
    int i = blockIdx.x * blockDim.x + threadIdx.x;
    int tot = B_ * (KP - K_) * N_;
    if (i < tot) {
        int b = i / ((KP - K_) * N_);
        int rem = i % ((KP - K_) * N_);
        long off = (long)b * KP * N_ + (long)K_ * N_ + rem;
        h16[off] = __float2half(0.f);
        hc16[off] = __float2half(0.f);
    }
}

// plain SIMT NT GEMM (M2 = cls @ W_feat^T)
__global__ void gemm_nt(const float* __restrict__ A, int lda,
                        const float* __restrict__ Bm, int ldb,
                        float* __restrict__ Cm, int ldc,
                        int M, int N, int Kin)
{
    __shared__ float As[16][65];
    __shared__ float Bs[16][65];
    int m0 = blockIdx.y * 64, n0 = blockIdx.x * 64;
    int tid = threadIdx.x;
    int tx = tid & 15, ty = tid >> 4;
    float acc[4][4] = {};

    for (int k0 = 0; k0 < Kin; k0 += 16) {
        #pragma unroll
        for (int j = 0; j < 4; j++) {
            int i = tid + j * 256;
            int m = i >> 4, k = i & 15;
            float v = 0.f;
            if (m0 + m < M && k0 + k < Kin) v = A[(long)(m0 + m) * lda + k0 + k];
            As[k][m] = v;
        }
        #pragma unroll
        for (int j = 0; j < 4; j++) {
            int i = tid + j * 256;
            int n = i >> 4, k = i & 15;
            float v = 0.f;
            if (n0 + n < N && k0 + k < Kin) v = Bm[(long)(n0 + n) * ldb + k0 + k];
            Bs[k][n] = v;
        }
        __syncthreads();
        #pragma unroll
        for (int kk = 0; kk < 16; kk++) {
            float a[4], bv[4];
            #pragma unroll
            for (int i = 0; i < 4; i++) a[i] = As[kk][ty + 16 * i];
            #pragma unroll
            for (int j = 0; j < 4; j++) bv[j] = Bs[kk][tx + 16 * j];
            #pragma unroll
            for (int i = 0; i < 4; i++)
                #pragma unroll
                for (int j = 0; j < 4; j++)
                    acc[i][j] += a[i] * bv[j];
        }
        __syncthreads();
    }

    #pragma unroll
    for (int i = 0; i < 4; i++) {
        int m = m0 + ty + 16 * i;
        if (m >= M) continue;
        #pragma unroll
        for (int j = 0; j < 4; j++) {
            int n = n0 + tx + 16 * j;
            if (n >= N) continue;
            Cm[(long)m * ldc + n] = acc[i][j];
        }
    }
}

// gemm_acls: acls[b] = cls + P[b] @ W_cls^T (fp32 + fp16 copies). grid (8,3,B_)
__global__ void gemm_acls(const float* __restrict__ P, const float* __restrict__ Wc,
                          const float* __restrict__ cls,
                          float* __restrict__ acls, __half* __restrict__ acls16)
{
    __shared__ float As[16][65];
    __shared__ float Bs[16][65];
    const float* Abp = P + (long)blockIdx.z * K_ * C_;
    float*  Cb  = acls   + (long)blockIdx.z * K_ * C_;
    __half* Cb16 = acls16 + (long)blockIdx.z * K_ * C_;
    int m0 = blockIdx.y * 64, n0 = blockIdx.x * 64;
    int tid = threadIdx.x;
    int tx = tid & 15, ty = tid >> 4;
    float acc[4][4] = {};

    for (int k0 = 0; k0 < C_; k0 += 16) {
        #pragma unroll
        for (int j = 0; j < 4; j++) {
            int i = tid + j * 256;
            int m = i >> 4, k = i & 15;
            float v = 0.f;
            if (m0 + m < K_) v = Abp[(long)(m0 + m) * C_ + k0 + k];
            As[k][m] = v;
        }
        #pragma unroll
        for (int j = 0; j < 4; j++) {
            int i = tid + j * 256;
            int n = i >> 4, k = i & 15;
            Bs[k][n] = Wc[(long)(n0 + n) * C_ + k0 + k];
        }
        __syncthreads();
        #pragma unroll
        for (int kk = 0; kk < 16; kk++) {
            float a[4], bv[4];
            #pragma unroll
            for (int i = 0; i < 4; i++) a[i] = As[kk][ty + 16 * i];
            #pragma unroll
            for (int j = 0; j < 4; j++) bv[j] = Bs[kk][tx + 16 * j];
            #pragma unroll
            for (int i = 0; i < 4; i++)
                #pragma unroll
                for (int j = 0; j < 4; j++)
                    acc[i][j] += a[i] * bv[j];
        }
        __syncthreads();
    }

    #pragma unroll
    for (int i = 0; i < 4; i++) {
        int m = m0 + ty + 16 * i;
        if (m >= K_) continue;
        #pragma unroll
        for (int j = 0; j < 4; j++) {
            int n = n0 + tx + 16 * j;
            float v = acc[i][j] + cls[(long)m * C_ + n];
            Cb[(long)m * C_ + n] = v;
            Cb16[(long)m * C_ + n] = __float2half_rn(v);
        }
    }
}

// gemm_STT: STT16[b][k'][k] = fp16( sum_d acls[b][k'][d]*M2[k][d] ), cols
// padded to KP with zeros. grid (3,3,B_)
__global__ void gemm_STT(const float* __restrict__ acls, const float* __restrict__ M2,
                         __half* __restrict__ STT16)
{
    __shared__ float As[16][65];
    __shared__ float Bs[16][65];
    const float* Abp = acls + (long)blockIdx.z * K_ * C_;
    __half*      Cb  = STT16 + (long)blockIdx.z * K_ * KP;
    int m0 = blockIdx.y * 64, n0 = blockIdx.x * 64;
    int tid = threadIdx.x;
    int tx = tid & 15, ty = tid >> 4;
    float acc[4][4] = {};

    for (int k0 = 0; k0 < C_; k0 += 16) {
        #pragma unroll
        for (int j = 0; j < 4; j++) {
            int i = tid + j * 256;
            int m = i >> 4, k = i & 15;
            float v = 0.f;
            if (m0 + m < K_) v = Abp[(long)(m0 + m) * C_ + k0 + k];
            As[k][m] = v;
        }
        #pragma unroll
        for (int j = 0; j < 4; j++) {
            int i = tid + j * 256;
            int n = i >> 4, k = i & 15;
            float v = 0.f;
            if (n0 + n < K_) v = M2[(long)(n0 + n) * C_ + k0 + k];
            Bs[k][n] = v;
        }
        __syncthreads();
        #pragma unroll
        for (int kk = 0; kk < 16; kk++) {
            float a[4], bv[4];
            #pragma unroll
            for (int i = 0; i < 4; i++) a[i] = As[kk][ty + 16 * i];
            #pragma unroll
            for (int j = 0; j < 4; j++) bv[j] = Bs[kk][tx + 16 * j];
            #pragma unroll
            for (int i = 0; i < 4; i++)
                #pragma unroll
                for (int j = 0; j < 4; j++)
                    acc[i][j] += a[i] * bv[j];
        }
        __syncthreads();
    }

    #pragma unroll
    for (int i = 0; i < 4; i++) {
        int m = m0 + ty + 16 * i;
        if (m >= K_) continue;
        #pragma unroll
        for (int j = 0; j < 4; j++) {
            int n = n0 + tx + 16 * j;
            if (n >= KP) continue;
            float v = (n < K_) ? acc[i][j] : 0.f;
            Cb[(long)m * KP + n] = __float2half_rn(v);
        }
    }
}

// ---------------------------------------------------------------------------
// kernel_launch
// ---------------------------------------------------------------------------
extern "C" void kernel_launch(void* const* d_in, const int* in_sizes, int n_in,
                              void* d_out, int out_size)
{
    const float* x      = (const float*)d_in[0];
    const float* cls    = (const float*)d_in[1];
    const float* W_cls  = (const float*)d_in[2];
    const float* W_feat = (const float*)d_in[3];
    const float* gamma  = (const float*)d_in[4];
    const float* beta   = (const float*)d_in[5];
    float* out = (float*)d_out;

    __half *x16, *h16, *hc16, *cls16, *acls16, *STT16;
    float *P, *Ppart, *M2, *acls, *rpart, *rinv, *cinv;
    cudaGetSymbolAddress((void**)&x16,   g_x16);
    cudaGetSymbolAddress((void**)&h16,   g_h16);
    cudaGetSymbolAddress((void**)&hc16,  g_hc16);
    cudaGetSymbolAddress((void**)&cls16, g_cls16);
    cudaGetSymbolAddress((void**)&P,     g_P);
    cudaGetSymbolAddress((void**)&Ppart, g_Ppart);
    cudaGetSymbolAddress((void**)&M2,    g_M2);
    cudaGetSymbolAddress((void**)&acls,  g_acls);
    cudaGetSymbolAddress((void**)&acls16, g_acls16);
    cudaGetSymbolAddress((void**)&STT16, g_STT16);
    cudaGetSymbolAddress((void**)&rpart, g_rpart);
    cudaGetSymbolAddress((void**)&rinv,  g_rinv);
    cudaGetSymbolAddress((void**)&cinv,  g_cinv);

    cudaFuncSetAttribute(k_attn,  cudaFuncAttributeMaxDynamicSharedMemorySize, SMEM_ATTN_B);
    cudaFuncSetAttribute(k2_pgemm, cudaFuncAttributeMaxDynamicSharedMemorySize, SMEM_K2_B);
    cudaFuncSetAttribute(k_masks, cudaFuncAttributeMaxDynamicSharedMemorySize, SMEM_MASK_B);

    // prep
    conv_cls16<<<(K_ * C_ + 255) / 256, 256>>>(cls, cls16);
    zero_hpad<<<(B_ * (KP - K_) * N_ + 255) / 256, 256>>>(h16, hc16);
    gemm_nt<<<dim3(8, 3, 1), 256>>>(cls, C_, W_feat, C_, M2, C_, K_, C_, C_);

    // h16/hc16 = exp(attn) (+cinv scaled); x16 emitted; row partials; cinv
    k_attn<<<dim3(N_ / BM, 1, B_), 256, SMEM_ATTN_B>>>(
        x, cls16, x16, h16, hc16, rpart, cinv);
    reduce_rinv<<<(B_ * K_ + 255) / 256, 256>>>(rpart, rinv);

    // P = rowsoftmax @ img_feat (fp16 mma, unnormalized; scaled in reduce)
    k2_pgemm<<<dim3(C_ / BM, NSPLIT, B_), 256, SMEM_K2_B>>>(x16, h16, Ppart);
    reduce_P<<<(B_ * K_ * C_ + 255) / 256, 256>>>(Ppart, rinv, P);

    // acls = cls + P @ W_cls^T (fp32 + fp16); STT16 = fp16(acls @ M2^T) padded
    gemm_acls<<<dim3(8, 3, B_), 256>>>(P, W_cls, cls, acls, acls16);
    gemm_STT<<<dim3(3, 3, B_), 256>>>(acls, M2, STT16);

    // out = LN( acls·x + ST·hc )   (fp16 mma, uniform 21-tile pipeline)
    k_masks<<<dim3(N_ / BM, 1, B_), 256, SMEM_MASK_B>>>(
        x16, acls16, STT16, hc16, gamma, beta, out);
}

// round 16
// speedup vs baseline: 1.5903x; 1.0188x over previous
#include <cuda_runtime.h>
#include <cuda_fp16.h>
#include <cstdint>

// Problem constants
#define B_  8
#define C_  512
#define N_  16384
#define K_  150
#define KP  160          // K padded
#define NSPLIT 8
#define CHUNK (N_ / NSPLIT)   // 2048

// Tile config
#define BM  128
#define BN  160
#define BK  32
#define BMp 136   // [k][m] pad (halves)
#define BKh 40    // fp16 [.][k] pad (halves)

// k_attn stage (words): As16 [32][BMp] + Bs16 [160][BKh]
#define STG_AK ((32 * BMp + BN * BKh) / 2)    // 2176 + 3200 = 5376 words
#define ABK    (32 * BMp / 2)                 // 2176 words

// k2 stage: As 128*BKh/2 + Bs 160*BKh/2  (words)
#define STG_2 ((BM * BKh + BN * BKh) / 2)     // 5760
#define AB2   (BM * BKh / 2)                  // 2560 words
// k_masks stage: As 32*BMp/2 + Bs 160*BKh/2 (words)
#define STG_M ((32 * BMp + BN * BKh) / 2)     // 5376
#define ABM   (32 * BMp / 2)                  // 2176 words

#define CS_W  (BN * BMp)                      // 21760 words
#define SMEM_ATTN_B  ((CS_W + 128) * 4)
#define SMEM_K2_B    (CS_W * 4)
#define MU_OFF  CS_W
#define RS_OFF  (CS_W + 128)
#define CI_OFF  (CS_W + 256)
#define SMEM_MASK_B  ((CS_W + 384) * 4)

// ---------------------------------------------------------------------------
// Device scratch
// ---------------------------------------------------------------------------
__device__ __half g_x16 [B_ * C_ * N_];     // fp16 x, written by k_attn
__device__ __half g_h16 [B_ * KP * N_];     // raw exp(attn), pad rows zero
__device__ __half g_cls16[K_ * C_];
__device__ float  g_P   [B_ * K_ * C_];
__device__ float  g_Ppart[NSPLIT * B_ * K_ * C_];
__device__ float  g_M2  [K_ * C_];
__device__ float  g_acls[B_ * K_ * C_];
__device__ __half g_acls16[B_ * K_ * C_];
__device__ __half g_STT16 [B_ * K_ * KP];   // cols >=150 zero
__device__ float  g_rpart[B_ * 128 * KP];
__device__ float  g_rinv[B_ * K_];
__device__ float  g_cinv[B_ * N_];

// ---------------------------------------------------------------------------
// helpers
// ---------------------------------------------------------------------------
__device__ __forceinline__ void mma16(float* c,
                                      uint32_t a0, uint32_t a1, uint32_t a2, uint32_t a3,
                                      uint32_t b0, uint32_t b1) {
    asm("mma.sync.aligned.m16n8k16.row.col.f32.f16.f16.f32 "
        "{%0,%1,%2,%3}, {%4,%5,%6,%7}, {%8,%9}, {%0,%1,%2,%3};"
        : "+f"(c[0]), "+f"(c[1]), "+f"(c[2]), "+f"(c[3])
        : "r"(a0), "r"(a1), "r"(a2), "r"(a3), "r"(b0), "r"(b1));
}
__device__ __forceinline__ void ldmx4(uint32_t& r0, uint32_t& r1, uint32_t& r2, uint32_t& r3,
                                      uint32_t addr) {
    asm volatile("ldmatrix.sync.aligned.m8n8.x4.shared.b16 {%0,%1,%2,%3}, [%4];"
                 : "=r"(r0), "=r"(r1), "=r"(r2), "=r"(r3) : "r"(addr));
}
__device__ __forceinline__ void ldmx4t(uint32_t& r0, uint32_t& r1, uint32_t& r2, uint32_t& r3,
                                       uint32_t addr) {
    asm volatile("ldmatrix.sync.aligned.m8n8.x4.trans.shared.b16 {%0,%1,%2,%3}, [%4];"
                 : "=r"(r0), "=r"(r1), "=r"(r2), "=r"(r3) : "r"(addr));
}
__device__ __forceinline__ void ldmx2(uint32_t& r0, uint32_t& r1, uint32_t addr) {
    asm volatile("ldmatrix.sync.aligned.m8n8.x2.shared.b16 {%0,%1}, [%2];"
                 : "=r"(r0), "=r"(r1) : "r"(addr));
}
__device__ __forceinline__ void cpa16(const void* smem, const void* gmem) {
    uint32_t s = (uint32_t)__cvta_generic_to_shared(smem);
    asm volatile("cp.async.cg.shared.global [%0], [%1], 16;" :: "r"(s), "l"(gmem));
}
#define CPA_COMMIT asm volatile("cp.async.commit_group;")
#define CPA_WAIT0  asm volatile("cp.async.wait_group 0;")

// ---------------------------------------------------------------------------
// k_attn (fp16 mma, register-prefetched x): h16 = exp(cls·x); emits x16,
// row partial sums, cinv. m=pixel(128), n=class(160). 256 thr, warps 4x2.
// Single sync per tile; x tile LDG'd one full tile ahead.
// grid (N_/BM, 1, B_)
// ---------------------------------------------------------------------------
__global__ __launch_bounds__(256, 2) void k_attn(
    const float* __restrict__ x, const __half* __restrict__ cls16,
    __half* __restrict__ x16, __half* __restrict__ h16,
    float* __restrict__ rpart, float* __restrict__ cinv)
{
    extern __shared__ uint32_t sm[];
    float* Cs = (float*)sm;

    const int tid = threadIdx.x, lane = tid & 31, warp = tid >> 5;
    const int wm = (warp & 3) * 32, wn = (warp >> 2) * 80;
    const int m0 = blockIdx.x * BM;
    const int b  = blockIdx.z;
    const float* Xb   = x   + (long)b * C_ * N_;
    __half*      X16b = x16 + (long)b * C_ * N_;

    const int xr = tid >> 3, xs = tid & 7;     // row 0..31, seg 0..7 (16 floats)

    float4 xa[4];
    auto ldg = [&](int kt) {
        const float* p = Xb + (long)(kt * BK + xr) * N_ + m0 + xs * 16;
        xa[0] = *(const float4*)p;       xa[1] = *(const float4*)(p + 4);
        xa[2] = *(const float4*)(p + 8); xa[3] = *(const float4*)(p + 12);
    };
    auto cvst = [&](int kt, int st) {          // regs -> fp16 smem + x16 global
        __half hv[16];
        #pragma unroll
        for (int q = 0; q < 4; q++) {
            hv[q*4    ] = __float2half_rn(((const float*)&xa[q])[0]);
            hv[q*4 + 1] = __float2half_rn(((const float*)&xa[q])[1]);
            hv[q*4 + 2] = __float2half_rn(((const float*)&xa[q])[2]);
            hv[q*4 + 3] = __float2half_rn(((const float*)&xa[q])[3]);
        }
        __half* d16 = (__half*)(sm + st * STG_AK) + xr * BMp + xs * 16;
        *(uint4*)d16       = *(uint4*)hv;
        *(uint4*)(d16 + 8) = *(uint4*)(hv + 8);
        __half* g = X16b + (long)(kt * BK + xr) * N_ + m0 + xs * 16;
        *(uint4*)g       = *(uint4*)hv;
        *(uint4*)(g + 8) = *(uint4*)(hv + 8);
    };
    auto cpaB = [&](int kt, int st) {
        __half* Bs16 = (__half*)(sm + st * STG_AK + ABK);
        const int k0 = kt * BK;
        #pragma unroll
        for (int p = 0; p < 3; p++) {
            int slot = tid + p * 256;
            if (slot < K_ * 4) {
                int r = slot >> 2, c = slot & 3;
                cpa16(Bs16 + r * BKh + c * 8, cls16 + (long)r * C_ + k0 + c * 8);
            }
        }
        CPA_COMMIT;
    };

    // prologue: tile0 fully staged; tile1 regs in flight
    ldg(0);
    cvst(0, 0);
    cpaB(0, 0);
    ldg(1);

    float acc[2][10][4] = {};
    const int KT = C_ / BK;                             // 16
    for (int kt = 0; kt < KT; kt++) {
        const int cur = kt & 1;
        CPA_WAIT0;
        __syncthreads();       // As16(cur) stores + Bs16(cur) cp.async visible
        if (kt + 1 < KT) {
            cvst(kt + 1, cur ^ 1);                      // uses regs from ldg(kt+1)
            cpaB(kt + 1, cur ^ 1);
        }
        if (kt + 2 < KT) ldg(kt + 2);

        uint32_t abase = (uint32_t)__cvta_generic_to_shared(
            (__half*)(sm + cur * STG_AK));
        uint32_t bbase = (uint32_t)__cvta_generic_to_shared(
            (__half*)(sm + cur * STG_AK + ABK));
        #pragma unroll
        for (int ks = 0; ks < 2; ks++) {
            uint32_t a[2][4], bb[20];
            #pragma unroll
            for (int mi = 0; mi < 2; mi++) {            // A from [k][m]: x4.trans
                int krow = ks * 16 + (lane & 7) + ((lane >> 4) & 1) * 8;
                int moff = wm + mi * 16 + ((lane >> 3) & 1) * 8;
                ldmx4t(a[mi][0], a[mi][1], a[mi][2], a[mi][3],
                       abase + (krow * BMp + moff) * 2);
            }
            #pragma unroll
            for (int bj = 0; bj < 5; bj++) {            // B from [n][k]: normal x4
                int nrow = wn + bj * 16 + (lane & 7) + ((lane >> 4) & 1) * 8;
                int col = ks * 16 + ((lane >> 3) & 1) * 8;
                ldmx4(bb[bj * 4], bb[bj * 4 + 1], bb[bj * 4 + 2], bb[bj * 4 + 3],
                      bbase + (nrow * BKh + col) * 2);
            }
            #pragma unroll
            for (int mi = 0; mi < 2; mi++)
                #pragma unroll
                for (int ni = 0; ni < 10; ni++)
                    mma16(acc[mi][ni], a[mi][0], a[mi][1], a[mi][2], a[mi][3],
                          bb[2 * ni], bb[2 * ni + 1]);
        }
    }
    __syncthreads();

    // stage h = exp(acc) into Cs[class][pixel]
    #pragma unroll
    for (int mi = 0; mi < 2; mi++)
        #pragma unroll
        for (int ni = 0; ni < 10; ni++) {
            int mr = wm + mi * 16 + (lane >> 2);
            int nc = wn + ni * 8 + (lane & 3) * 2;
            Cs[ nc      * BMp + mr    ] = expf(acc[mi][ni][0]);
            Cs[(nc + 1) * BMp + mr    ] = expf(acc[mi][ni][1]);
            Cs[ nc      * BMp + mr + 8] = expf(acc[mi][ni][2]);
            Cs[(nc + 1) * BMp + mr + 8] = expf(acc[mi][ni][3]);
        }
    __syncthreads();

    if (tid < BM) {
        float s = 0.f;
        for (int k = 0; k < K_; k++) s += Cs[k * BMp + tid];
        cinv[(long)b * N_ + m0 + tid] = 1.f / s;
    }

    __half* Hb = h16 + (long)b * KP * N_;
    #pragma unroll
    for (int i = 0; i < 19; i++) {
        int r = warp + i * 8;
        if (r < K_) {
            int ml = lane * 4;
            float4 v = *(float4*)(Cs + r * BMp + ml);
            __half2 p0 = __floats2half2_rn(v.x, v.y);
            __half2 p1 = __floats2half2_rn(v.z, v.w);
            *(uint2*)(Hb + (long)r * N_ + m0 + ml) =
                make_uint2(*(uint32_t*)&p0, *(uint32_t*)&p1);
            float s = v.x + v.y + v.z + v.w;
            #pragma unroll
            for (int o = 16; o > 0; o >>= 1) s += __shfl_xor_sync(0xffffffffu, s, o);
            if (lane == 0) rpart[((long)b * 128 + blockIdx.x) * KP + r] = s;
        }
    }
}

// ---------------------------------------------------------------------------
// k2_pgemm (fp16): Ppart[split][b][k][c] = sum_pix h16[k][pix]*x16[c][pix]
// m=channel(128), n=class(160). warps 2(m)x4(n); acc[4][5][4].
// grid (4, NSPLIT, B_)
// ---------------------------------------------------------------------------
__global__ __launch_bounds__(256, 2) void k2_pgemm(
    const __half* __restrict__ x16, const __half* __restrict__ h16,
    float* __restrict__ Pp)
{
    extern __shared__ uint32_t sm[];
    float* Cs = (float*)sm;

    const int tid = threadIdx.x, lane = tid & 31, warp = tid >> 5;
    const int wm = (warp & 1) * 64, wn = (warp >> 1) * 40;
    const int m0 = blockIdx.x * BM;
    const int split = blockIdx.y, b = blockIdx.z;
    const __half* Xb = x16 + (long)b * C_ * N_;
    const __half* Hb = h16 + (long)b * KP * N_;

    const int kbeg = split * CHUNK;
    auto issue = [&](int kt, int st) {
        __half* As16 = (__half*)(sm + st * STG_2);
        __half* Bs16 = (__half*)(sm + st * STG_2 + AB2);
        const int k0 = kbeg + kt * BK;
        #pragma unroll
        for (int p = 0; p < 2; p++) {                   // [m][k]
            int slot = tid + p * 256;
            int r = slot >> 2, c = slot & 3;
            cpa16(As16 + r * BKh + c * 8, Xb + (long)(m0 + r) * N_ + k0 + c * 8);
        }
        #pragma unroll
        for (int p = 0; p < 3; p++) {                   // [n][k]
            int slot = tid + p * 256;
            if (slot < KP * 4) {
                int r = slot >> 2, c = slot & 3;
                cpa16(Bs16 + r * BKh + c * 8, Hb + (long)r * N_ + k0 + c * 8);
            }
        }
        CPA_COMMIT;
    };

    issue(0, 0);
    float acc[4][5][4] = {};
    const int KT = CHUNK / BK;                          // 64
    for (int kt = 0; kt < KT; kt++) {
        const int cur = kt & 1;
        CPA_WAIT0;
        __syncthreads();
        if (kt + 1 < KT) issue(kt + 1, cur ^ 1);
        uint32_t abase = (uint32_t)__cvta_generic_to_shared((__half*)(sm + cur * STG_2));
        uint32_t bbase = (uint32_t)__cvta_generic_to_shared((__half*)(sm + cur * STG_2 + AB2));
        #pragma unroll
        for (int ks = 0; ks < 2; ks++) {                // k16 per step
            uint32_t a[4][4], bb[10];
            #pragma unroll
            for (int mi = 0; mi < 4; mi++) {
                int row = wm + mi * 16 + (lane & 7) + ((lane >> 3) & 1) * 8;
                int col = ks * 16 + ((lane >> 4) & 1) * 8;
                ldmx4(a[mi][0], a[mi][1], a[mi][2], a[mi][3],
                      abase + (row * BKh + col) * 2);
            }
            #pragma unroll
            for (int bj = 0; bj < 2; bj++) {
                int nrow = wn + bj * 16 + (lane & 7) + ((lane >> 4) & 1) * 8;
                int col = ks * 16 + ((lane >> 3) & 1) * 8;
                ldmx4(bb[bj * 4], bb[bj * 4 + 1], bb[bj * 4 + 2], bb[bj * 4 + 3],
                      bbase + (nrow * BKh + col) * 2);
            }
            {
                int nrow = wn + 32 + (lane & 7);
                int col = ks * 16 + ((lane >> 3) & 1) * 8;
                ldmx2(bb[8], bb[9], bbase + (nrow * BKh + col) * 2);
            }
            #pragma unroll
            for (int mi = 0; mi < 4; mi++)
                #pragma unroll
                for (int ni = 0; ni < 5; ni++)
                    mma16(acc[mi][ni], a[mi][0], a[mi][1], a[mi][2], a[mi][3],
                          bb[2 * ni], bb[2 * ni + 1]);
        }
    }
    __syncthreads();

    #pragma unroll
    for (int mi = 0; mi < 4; mi++)
        #pragma unroll
        for (int ni = 0; ni < 5; ni++) {
            int mr = wm + mi * 16 + (lane >> 2);
            int nc = wn + ni * 8 + (lane & 3) * 2;
            Cs[ nc      * BMp + mr    ] = acc[mi][ni][0];
            Cs[(nc + 1) * BMp + mr    ] = acc[mi][ni][1];
            Cs[ nc      * BMp + mr + 8] = acc[mi][ni][2];
            Cs[(nc + 1) * BMp + mr + 8] = acc[mi][ni][3];
        }
    __syncthreads();

    float* Pb = Pp + ((long)split * B_ + b) * K_ * C_;
    #pragma unroll
    for (int i = 0; i < 19; i++) {
        int r = warp + i * 8;
        if (r < K_) {
            float4 v = *(float4*)(Cs + r * BMp + lane * 4);
            *(float4*)(Pb + (long)r * C_ + m0 + lane * 4) = v;
        }
    }
}

// ---------------------------------------------------------------------------
// k_masks (fp16): out = LN_k( acls·x + ST·(h·cinv) ). 21 tiles:
// 0..15: A=x16 [k][m] (x4.trans), B=acls16; 16..20: A=h16 (cinv applied to
// fragments via HMUL2), B=STT16. grid (N_/BM, 1, B_)
// ---------------------------------------------------------------------------
__global__ __launch_bounds__(256, 2) void k_masks(
    const __half* __restrict__ x16, const __half* __restrict__ acls16,
    const __half* __restrict__ STT16, const __half* __restrict__ h16,
    const float* __restrict__ cinv,
    const float* __restrict__ gamma, const float* __restrict__ beta,
    float* __restrict__ out)
{
    extern __shared__ uint32_t sm[];
    float* Cs   = (float*)sm;
    float* mu_s = (float*)(sm + MU_OFF);
    float* rs_s = (float*)(sm + RS_OFF);
    float* ci_s = (float*)(sm + CI_OFF);

    const int tid = threadIdx.x, lane = tid & 31, warp = tid >> 5;
    const int wm = (warp & 3) * 32, wn = (warp >> 2) * 80;
    const int m0 = blockIdx.x * BM;
    const int b  = blockIdx.z;

    const __half* Xb = x16    + (long)b * C_ * N_;
    const __half* Ab = acls16 + (long)b * K_ * C_;
    const __half* Sb = STT16  + (long)b * K_ * KP;
    const __half* Hb = h16    + (long)b * KP * N_;

    if (tid < BM) ci_s[tid] = cinv[(long)b * N_ + m0 + tid];

    auto issue = [&](int kt, int st) {
        __half* As16 = (__half*)(sm + st * STG_M);
        __half* Bs16 = (__half*)(sm + st * STG_M + ABM);
        const __half* srcA; const __half* srcB; int k0, ldb;
        if (kt < 16) { srcA = Xb; srcB = Ab; k0 = kt * BK;        ldb = C_; }
        else         { srcA = Hb; srcB = Sb; k0 = (kt - 16) * BK; ldb = KP; }
        #pragma unroll
        for (int p = 0; p < 2; p++) {                   // [k][m]
            int slot = tid + p * 256;
            int r = slot >> 4, c = slot & 15;
            cpa16(As16 + r * BMp + c * 8, srcA + (long)(k0 + r) * N_ + m0 + c * 8);
        }
        #pragma unroll
        for (int p = 0; p < 3; p++) {                   // [n][k]
            int slot = tid + p * 256;
            if (slot < K_ * 4) {
                int r = slot >> 2, c = slot & 3;
                cpa16(Bs16 + r * BKh + c * 8, srcB + (long)r * ldb + k0 + c * 8);
            }
        }
        CPA_COMMIT;
    };

    issue(0, 0);
    float acc[2][10][4] = {};
    const int KT = 16 + 5;
    for (int kt = 0; kt < KT; kt++) {
        const int cur = kt & 1;
        CPA_WAIT0;
        __syncthreads();
        if (kt + 1 < KT) issue(kt + 1, cur ^ 1);
        uint32_t abase = (uint32_t)__cvta_generic_to_shared((__half*)(sm + cur * STG_M));
        uint32_t bbase = (uint32_t)__cvta_generic_to_shared((__half*)(sm + cur * STG_M + ABM));
        const bool ph1 = (kt >= 16);
        #pragma unroll
        for (int ks = 0; ks < 2; ks++) {
            uint32_t a[2][4], bb[20];
            #pragma unroll
            for (int mi = 0; mi < 2; mi++) {
                int krow = ks * 16 + (lane & 7) + ((lane >> 4) & 1) * 8;
                int moff = wm + mi * 16 + ((lane >> 3) & 1) * 8;
                ldmx4t(a[mi][0], a[mi][1], a[mi][2], a[mi][3],
                       abase + (krow * BMp + moff) * 2);
                if (ph1) {
                    // fragment rows: a0,a2 -> m = wm+mi*16+(lane>>2); a1,a3 -> +8
                    int g = wm + mi * 16 + (lane >> 2);
                    __half2 c0 = __float2half2_rn(ci_s[g]);
                    __half2 c1 = __float2half2_rn(ci_s[g + 8]);
                    *(__half2*)&a[mi][0] = __hmul2(*(__half2*)&a[mi][0], c0);
                    *(__half2*)&a[mi][1] = __hmul2(*(__half2*)&a[mi][1], c1);
                    *(__half2*)&a[mi][2] = __hmul2(*(__half2*)&a[mi][2], c0);
                    *(__half2*)&a[mi][3] = __hmul2(*(__half2*)&a[mi][3], c1);
                }
            }
            #pragma unroll
            for (int bj = 0; bj < 5; bj++) {
                int nrow = wn + bj * 16 + (lane & 7) + ((lane >> 4) & 1) * 8;
                int col = ks * 16 + ((lane >> 3) & 1) * 8;
                ldmx4(bb[bj * 4], bb[bj * 4 + 1], bb[bj * 4 + 2], bb[bj * 4 + 3],
                      bbase + (nrow * BKh + col) * 2);
            }
            #pragma unroll
            for (int mi = 0; mi < 2; mi++)
                #pragma unroll
                for (int ni = 0; ni < 10; ni++)
                    mma16(acc[mi][ni], a[mi][0], a[mi][1], a[mi][2], a[mi][3],
                          bb[2 * ni], bb[2 * ni + 1]);
        }
    }
    __syncthreads();

    #pragma unroll
    for (int mi = 0; mi < 2; mi++)
        #pragma unroll
        for (int ni = 0; ni < 10; ni++) {
            int mr = wm + mi * 16 + (lane >> 2);
            int nc = wn + ni * 8 + (lane & 3) * 2;
            Cs[ nc      * BMp + mr    ] = acc[mi][ni][0];
            Cs[(nc + 1) * BMp + mr    ] = acc[mi][ni][1];
            Cs[ nc      * BMp + mr + 8] = acc[mi][ni][2];
            Cs[(nc + 1) * BMp + mr + 8] = acc[mi][ni][3];
        }
    __syncthreads();

    if (tid < BM) {
        float s = 0.f, s2 = 0.f;
        for (int k = 0; k < K_; k++) {
            float v = Cs[k * BMp + tid];
            s += v; s2 += v * v;
        }
        float mu  = s * (1.f / K_);
        float var = s2 * (1.f / K_) - mu * mu;
        mu_s[tid] = mu;
        rs_s[tid] = rsqrtf(fmaxf(var, 0.f) + 1e-5f);
    }
    __syncthreads();

    float* Ob = out + (long)b * K_ * N_;
    #pragma unroll
    for (int i = 0; i < 19; i++) {
        int r = warp + i * 8;
        if (r < K_) {
            float g  = __ldg(&gamma[r]);
            float bt = __ldg(&beta[r]);
            int ml = lane * 4;
            float4 v = *(float4*)(Cs + r * BMp + ml);
            v.x = (v.x - mu_s[ml    ]) * rs_s[ml    ] * g + bt;
            v.y = (v.y - mu_s[ml + 1]) * rs_s[ml + 1] * g + bt;
            v.z = (v.z - mu_s[ml + 2]) * rs_s[ml + 2] * g + bt;
            v.w = (v.w - mu_s[ml + 3]) * rs_s[ml + 3] * g + bt;
            *(float4*)(Ob + (long)r * N_ + m0 + ml) = v;
        }
    }
}

// ---------------------------------------------------------------------------
// small kernels
// ---------------------------------------------------------------------------
__global__ void reduce_rinv(const float* __restrict__ rpart, float* __restrict__ rinv)
{
    int idx = blockIdx.x * blockDim.x + threadIdx.x;
    if (idx < B_ * K_) {
        int b = idx / K_, k = idx % K_;
        float s = 0.f;
        for (int blk = 0; blk < 128; blk++)
            s += rpart[((long)b * 128 + blk) * KP + k];
        rinv[idx] = 1.f / s;
    }
}

__global__ void reduce_P(const float* __restrict__ Pp, const float* __restrict__ rinv,
                         float* __restrict__ P)
{
    int i = blockIdx.x * blockDim.x + threadIdx.x;
    if (i < B_ * K_ * C_) {
        int b = i / (K_ * C_);
        int k = (i / C_) % K_;
        float s = 0.f;
        #pragma unroll
        for (int sp = 0; sp < NSPLIT; sp++) s += Pp[(long)sp * B_ * K_ * C_ + i];
        P[i] = s * rinv[b * K_ + k];
    }
}

__global__ void conv_cls16(const float* __restrict__ cls, __half* __restrict__ cls16)
{
    int i = blockIdx.x * blockDim.x + threadIdx.x;
    if (i < K_ * C_) cls16[i] = __float2half_rn(cls[i]);
}

__global__ void zero_hpad(__half* __restrict__ h16)
{
    int i = blockIdx.x * blockDim.x + threadIdx.x;
    int tot = B_ * (KP - K_) * N_;
    if (i < tot) {
        int b = i / ((KP - K_) * N_);
        int rem = i % ((KP - K_) * N_);
        h16[(long)b * KP * N_ + (long)K_ * N_ + rem] = __float2half(0.f);
    }
}

// plain SIMT NT GEMM (M2 = cls @ W_feat^T)
__global__ void gemm_nt(const float* __restrict__ A, int lda,
                        const float* __restrict__ Bm, int ldb,
                        float* __restrict__ Cm, int ldc,
                        int M, int N, int Kin)
{
    __shared__ float As[16][65];
    __shared__ float Bs[16][65];
    int m0 = blockIdx.y * 64, n0 = blockIdx.x * 64;
    int tid = threadIdx.x;
    int tx = tid & 15, ty = tid >> 4;
    float acc[4][4] = {};

    for (int k0 = 0; k0 < Kin; k0 += 16) {
        #pragma unroll
        for (int j = 0; j < 4; j++) {
            int i = tid + j * 256;
            int m = i >> 4, k = i & 15;
            float v = 0.f;
            if (m0 + m < M && k0 + k < Kin) v = A[(long)(m0 + m) * lda + k0 + k];
            As[k][m] = v;
        }
        #pragma unroll
        for (int j = 0; j < 4; j++) {
            int i = tid + j * 256;
            int n = i >> 4, k = i & 15;
            float v = 0.f;
            if (n0 + n < N && k0 + k < Kin) v = Bm[(long)(n0 + n) * ldb + k0 + k];
            Bs[k][n] = v;
        }
        __syncthreads();
        #pragma unroll
        for (int kk = 0; kk < 16; kk++) {
            float a[4], bv[4];
            #pragma unroll
            for (int i = 0; i < 4; i++) a[i] = As[kk][ty + 16 * i];
            #pragma unroll
            for (int j = 0; j < 4; j++) bv[j] = Bs[kk][tx + 16 * j];
            #pragma unroll
            for (int i = 0; i < 4; i++)
                #pragma unroll
                for (int j = 0; j < 4; j++)
                    acc[i][j] += a[i] * bv[j];
        }
        __syncthreads();
    }

    #pragma unroll
    for (int i = 0; i < 4; i++) {
        int m = m0 + ty + 16 * i;
        if (m >= M) continue;
        #pragma unroll
        for (int j = 0; j < 4; j++) {
            int n = n0 + tx + 16 * j;
            if (n >= N) continue;
            Cm[(long)m * ldc + n] = acc[i][j];
        }
    }
}

// gemm_acls: acls[b] = cls + P[b] @ W_cls^T (fp32 + fp16 copies). grid (8,3,B_)
__global__ void gemm_acls(const float* __restrict__ P, const float* __restrict__ Wc,
                          const float* __restrict__ cls,
                          float* __restrict__ acls, __half* __restrict__ acls16)
{
    __shared__ float As[16][65];
    __shared__ float Bs[16][65];
    const float* Abp = P + (long)blockIdx.z * K_ * C_;
    float*  Cb  = acls   + (long)blockIdx.z * K_ * C_;
    __half* Cb16 = acls16 + (long)blockIdx.z * K_ * C_;
    int m0 = blockIdx.y * 64, n0 = blockIdx.x * 64;
    int tid = threadIdx.x;
    int tx = tid & 15, ty = tid >> 4;
    float acc[4][4] = {};

    for (int k0 = 0; k0 < C_; k0 += 16) {
        #pragma unroll
        for (int j = 0; j < 4; j++) {
            int i = tid + j * 256;
            int m = i >> 4, k = i & 15;
            float v = 0.f;
            if (m0 + m < K_) v = Abp[(long)(m0 + m) * C_ + k0 + k];
            As[k][m] = v;
        }
        #pragma unroll
        for (int j = 0; j < 4; j++) {
            int i = tid + j * 256;
            int n = i >> 4, k = i & 15;
            Bs[k][n] = Wc[(long)(n0 + n) * C_ + k0 + k];
        }
        __syncthreads();
        #pragma unroll
        for (int kk = 0; kk < 16; kk++) {
            float a[4], bv[4];
            #pragma unroll
            for (int i = 0; i < 4; i++) a[i] = As[kk][ty + 16 * i];
            #pragma unroll
            for (int j = 0; j < 4; j++) bv[j] = Bs[kk][tx + 16 * j];
            #pragma unroll
            for (int i = 0; i < 4; i++)
                #pragma unroll
                for (int j = 0; j < 4; j++)
                    acc[i][j] += a[i] * bv[j];
        }
        __syncthreads();
    }

    #pragma unroll
    for (int i = 0; i < 4; i++) {
        int m = m0 + ty + 16 * i;
        if (m >= K_) continue;
        #pragma unroll
        for (int j = 0; j < 4; j++) {
            int n = n0 + tx + 16 * j;
            float v = acc[i][j] + cls[(long)m * C_ + n];
            Cb[(long)m * C_ + n] = v;
            Cb16[(long)m * C_ + n] = __float2half_rn(v);
        }
    }
}

// gemm_STT: STT16[b][k'][k] = fp16( sum_d acls[b][k'][d]*M2[k][d] ), cols
// padded to KP with zeros. grid (3,3,B_)
__global__ void gemm_STT(const float* __restrict__ acls, const float* __restrict__ M2,
                         __half* __restrict__ STT16)
{
    __shared__ float As[16][65];
    __shared__ float Bs[16][65];
    const float* Abp = acls + (long)blockIdx.z * K_ * C_;
    __half*      Cb  = STT16 + (long)blockIdx.z * K_ * KP;
    int m0 = blockIdx.y * 64, n0 = blockIdx.x * 64;
    int tid = threadIdx.x;
    int tx = tid & 15, ty = tid >> 4;
    float acc[4][4] = {};

    for (int k0 = 0; k0 < C_; k0 += 16) {
        #pragma unroll
        for (int j = 0; j < 4; j++) {
            int i = tid + j * 256;
            int m = i >> 4, k = i & 15;
            float v = 0.f;
            if (m0 + m < K_) v = Abp[(long)(m0 + m) * C_ + k0 + k];
            As[k][m] = v;
        }
        #pragma unroll
        for (int j = 0; j < 4; j++) {
            int i = tid + j * 256;
            int n = i >> 4, k = i & 15;
            float v = 0.f;
            if (n0 + n < K_) v = M2[(long)(n0 + n) * C_ + k0 + k];
            Bs[k][n] = v;
        }
        __syncthreads();
        #pragma unroll
        for (int kk = 0; kk < 16; kk++) {
            float a[4], bv[4];
            #pragma unroll
            for (int i = 0; i < 4; i++) a[i] = As[kk][ty + 16 * i];
            #pragma unroll
            for (int j = 0; j < 4; j++) bv[j] = Bs[kk][tx + 16 * j];
            #pragma unroll
            for (int i = 0; i < 4; i++)
                #pragma unroll
                for (int j = 0; j < 4; j++)
                    acc[i][j] += a[i] * bv[j];
        }
        __syncthreads();
    }

    #pragma unroll
    for (int i = 0; i < 4; i++) {
        int m = m0 + ty + 16 * i;
        if (m >= K_) continue;
        #pragma unroll
        for (int j = 0; j < 4; j++) {
            int n = n0 + tx + 16 * j;
            if (n >= KP) continue;
            float v = (n < K_) ? acc[i][j] : 0.f;
            Cb[(long)m * KP + n] = __float2half_rn(v);
        }
    }
}

// ---------------------------------------------------------------------------
// kernel_launch
// ---------------------------------------------------------------------------
extern "C" void kernel_launch(void* const* d_in, const int* in_sizes, int n_in,
                              void* d_out, int out_size)
{
    const float* x      = (const float*)d_in[0];
    const float* cls    = (const float*)d_in[1];
    const float* W_cls  = (const float*)d_in[2];
    const float* W_feat = (const float*)d_in[3];
    const float* gamma  = (const float*)d_in[4];
    const float* beta   = (const float*)d_in[5];
    float* out = (float*)d_out;

    __half *x16, *h16, *cls16, *acls16, *STT16;
    float *P, *Ppart, *M2, *acls, *rpart, *rinv, *cinv;
    cudaGetSymbolAddress((void**)&x16,   g_x16);
    cudaGetSymbolAddress((void**)&h16,   g_h16);
    cudaGetSymbolAddress((void**)&cls16, g_cls16);
    cudaGetSymbolAddress((void**)&P,     g_P);
    cudaGetSymbolAddress((void**)&Ppart, g_Ppart);
    cudaGetSymbolAddress((void**)&M2,    g_M2);
    cudaGetSymbolAddress((void**)&acls,  g_acls);
    cudaGetSymbolAddress((void**)&acls16, g_acls16);
    cudaGetSymbolAddress((void**)&STT16, g_STT16);
    cudaGetSymbolAddress((void**)&rpart, g_rpart);
    cudaGetSymbolAddress((void**)&rinv,  g_rinv);
    cudaGetSymbolAddress((void**)&cinv,  g_cinv);

    cudaFuncSetAttribute(k_attn,  cudaFuncAttributeMaxDynamicSharedMemorySize, SMEM_ATTN_B);
    cudaFuncSetAttribute(k2_pgemm, cudaFuncAttributeMaxDynamicSharedMemorySize, SMEM_K2_B);
    cudaFuncSetAttribute(k_masks, cudaFuncAttributeMaxDynamicSharedMemorySize, SMEM_MASK_B);

    // prep
    conv_cls16<<<(K_ * C_ + 255) / 256, 256>>>(cls, cls16);
    zero_hpad<<<(B_ * (KP - K_) * N_ + 255) / 256, 256>>>(h16);
    gemm_nt<<<dim3(8, 3, 1), 256>>>(cls, C_, W_feat, C_, M2, C_, K_, C_, C_);

    // h16 = exp(attn); x16 emitted; row partials; cinv
    k_attn<<<dim3(N_ / BM, 1, B_), 256, SMEM_ATTN_B>>>(
        x, cls16, x16, h16, rpart, cinv);
    reduce_rinv<<<(B_ * K_ + 255) / 256, 256>>>(rpart, rinv);

    // P = rowsoftmax @ img_feat (fp16 mma, unnormalized; scaled in reduce)
    k2_pgemm<<<dim3(C_ / BM, NSPLIT, B_), 256, SMEM_K2_B>>>(x16, h16, Ppart);
    reduce_P<<<(B_ * K_ * C_ + 255) / 256, 256>>>(Ppart, rinv, P);

    // acls = cls + P @ W_cls^T (fp32 + fp16); STT16 = fp16(acls @ M2^T) padded
    gemm_acls<<<dim3(8, 3, B_), 256>>>(P, W_cls, cls, acls, acls16);
    gemm_STT<<<dim3(3, 3, B_), 256>>>(acls, M2, STT16);

    // out = LN( acls·x + ST·(h·cinv) )   (fp16 mma; cinv folded into A frags)
    k_masks<<<dim3(N_ / BM, 1, B_), 256, SMEM_MASK_B>>>(
        x16, acls16, STT16, h16, cinv, gamma, beta, out);
}